// round 10
// baseline (speedup 1.0000x reference)
#include <cuda_runtime.h>
#include <cuda_bf16.h>
#include <cstdint>
#include <math.h>

// ---------------- problem constants ----------------
#define NIMG 16
#define CDIM 512
#define HDIM 32
#define WDIM 32
#define TTOK (NIMG*HDIM*WDIM)      // 16384
#define MEMN 2000
#define MEMP 2048                   // padded
#define CHID 256
#define SHRINK 0.0025f
#define EPSV 1e-12f

#define OUT_ELEMS ((size_t)NIMG*CDIM*HDIM*WDIM)   // 8388608

// row stride for bf16 tiles: 40 halfs = 20 words (conflict-free fragment loads)
#define HSTRIDE 40
#define WSTRIDE 20

// ---------------- scratch (device globals) ----------------
__device__ __nv_bfloat16 g_qb[(size_t)TTOK * CDIM];       // bf16 queries [T,C]
__device__ float g_h[(size_t)MEMN * CHID];                 // MLP hidden (fp32)
__device__ float g_m[(size_t)MEMN * CDIM];                 // MLP out (pre-norm, fp32)
__device__ __nv_bfloat16 g_mnormb[(size_t)MEMP * CDIM];   // normalized memory [J,C] bf16, zero pad
__device__ __nv_bfloat16 g_mnormTb[(size_t)CDIM * MEMP];  // transposed [C,J] bf16, zero pad
__device__ float g_Z[TTOK];
__device__ int   g_flags[(TTOK / 128) * 64];               // per (token-tile, 32-mem stage) activity

#define MMA_BF16(c, a, b) \
    asm volatile("mma.sync.aligned.m16n8k16.row.col.f32.bf16.bf16.f32 " \
        "{%0,%1,%2,%3}, {%4,%5,%6,%7}, {%8,%9}, {%0,%1,%2,%3};" \
        : "+f"((c)[0]), "+f"((c)[1]), "+f"((c)[2]), "+f"((c)[3]) \
        : "r"((a)[0]), "r"((a)[1]), "r"((a)[2]), "r"((a)[3]), \
          "r"((b)[0]), "r"((b)[1]))

__device__ __forceinline__ void cp16(uint32_t dst, const void* src) {
    asm volatile("cp.async.ca.shared.global [%0], [%1], 16;" :: "r"(dst), "l"(src) : "memory");
}
#define CP_COMMIT() asm volatile("cp.async.commit_group;" ::: "memory")
#define CP_WAIT1()  asm volatile("cp.async.wait_group 1;" ::: "memory")
#define CP_WAIT0()  asm volatile("cp.async.wait_group 0;" ::: "memory")

// ---------------- kernel: zero Z ----------------
__global__ void zero_z_kernel() {
    int i = blockIdx.x * blockDim.x + threadIdx.x;
    if (i < TTOK) g_Z[i] = 0.0f;
}

// ---------------- kernel: build q (NCHW -> [T,C], L2 normalized, bf16) ----------------
__global__ void build_q_kernel(const float* __restrict__ x) {
    int bid = blockIdx.x;
    int n = bid >> 5, h = bid & 31;
    int tid = threadIdx.x;
    int w = tid & 31, cg = tid >> 5;

    __shared__ float ss[8][32];
    __shared__ float inv[32];
    __shared__ float xt[32][33];

    const float* xb = x + (size_t)n * (CDIM * HDIM * WDIM) + h * WDIM;

    float part = 0.0f;
    for (int c = cg; c < CDIM; c += 8) {
        float v = xb[c * 1024 + w];
        part += v * v;
    }
    ss[cg][w] = part;
    __syncthreads();
    if (tid < 32) {
        float s = 0.0f;
        #pragma unroll
        for (int g = 0; g < 8; g++) s += ss[g][tid];
        inv[tid] = 1.0f / fmaxf(sqrtf(s), EPSV);
    }
    __syncthreads();

    int t0 = n * 1024 + h * 32;
    int cl = tid & 31, tg = tid >> 5;
    for (int c0 = 0; c0 < CDIM; c0 += 32) {
        for (int ci = cg; ci < 32; ci += 8)
            xt[ci][w] = xb[(c0 + ci) * 1024 + w];
        __syncthreads();
        for (int tl = tg; tl < 32; tl += 8)
            g_qb[(size_t)(t0 + tl) * CDIM + c0 + cl] = __float2bfloat16(xt[cl][tl] * inv[tl]);
        __syncthreads();
    }
}

// ---------------- kernel: MLP GEMM  C = relu(A @ B^T + bias)  (SIMT fp32) ----------------
// transposed smem tiles [kk][row] (stride 68) -> inner loop uses 2x LDS.128 per kk
__global__ void mlp_gemm_kernel(const float* __restrict__ extA,
                                const float* __restrict__ Bw,
                                const float* __restrict__ bias,
                                int layer) {
    const float* A = layer ? (const float*)g_h : extA;
    float* Cc      = layer ? g_m : g_h;
    const int M = MEMN;
    const int N = layer ? CDIM : CHID;
    const int K = layer ? CHID : CDIM;

    int n0 = blockIdx.x * 64;
    int m0 = blockIdx.y * 64;

    __shared__ float As[32][68];
    __shared__ float Bs[32][68];

    int tid = threadIdx.x;
    int tx = tid & 15, ty = tid >> 4;
    float acc[4][4] = {};

    for (int k0 = 0; k0 < K; k0 += 32) {
        for (int idx = tid; idx < 512; idx += 256) {
            int r = idx >> 3, kq = (idx & 7) << 2;
            float4 v = make_float4(0.f, 0.f, 0.f, 0.f);
            if (m0 + r < M) v = *(const float4*)&A[(size_t)(m0 + r) * K + k0 + kq];
            As[kq + 0][r] = v.x; As[kq + 1][r] = v.y; As[kq + 2][r] = v.z; As[kq + 3][r] = v.w;
            float4 w = *(const float4*)&Bw[(size_t)(n0 + r) * K + k0 + kq];
            Bs[kq + 0][r] = w.x; Bs[kq + 1][r] = w.y; Bs[kq + 2][r] = w.z; Bs[kq + 3][r] = w.w;
        }
        __syncthreads();
        #pragma unroll
        for (int kk = 0; kk < 32; kk++) {
            float a[4], b[4];
            *(float4*)a = *(const float4*)&As[kk][tx * 4];
            *(float4*)b = *(const float4*)&Bs[kk][ty * 4];
            #pragma unroll
            for (int i = 0; i < 4; i++)
                #pragma unroll
                for (int j = 0; j < 4; j++)
                    acc[i][j] += a[i] * b[j];
        }
        __syncthreads();
    }

    #pragma unroll
    for (int j = 0; j < 4; j++) {
        int col = n0 + ty * 4 + j;
        float bv = bias[col];
        #pragma unroll
        for (int i = 0; i < 4; i++) {
            int row = m0 + tx * 4 + i;
            if (row < M) Cc[(size_t)row * N + col] = fmaxf(acc[i][j] + bv, 0.0f);
        }
    }
}

// ---------------- kernel: row L2-normalize m -> g_mnormb (bf16, zero pad) ----------------
__global__ void norm_rows_kernel() {
    int row = blockIdx.x;
    int tid = threadIdx.x;
    __nv_bfloat16* dst = &g_mnormb[(size_t)row * CDIM];
    if (row >= MEMN) {
        dst[tid] = __float2bfloat16(0.0f);
        dst[tid + 256] = __float2bfloat16(0.0f);
        return;
    }
    const float* src = &g_m[(size_t)row * CDIM];
    float v0 = src[tid], v1 = src[tid + 256];
    float ssv = v0 * v0 + v1 * v1;
    #pragma unroll
    for (int o = 16; o > 0; o >>= 1) ssv += __shfl_down_sync(0xffffffffu, ssv, o);
    __shared__ float red[8];
    __shared__ float sinv;
    if ((tid & 31) == 0) red[tid >> 5] = ssv;
    __syncthreads();
    if (tid == 0) {
        float s = 0.0f;
        #pragma unroll
        for (int i = 0; i < 8; i++) s += red[i];
        sinv = 1.0f / fmaxf(sqrtf(s), EPSV);
    }
    __syncthreads();
    dst[tid] = __float2bfloat16(v0 * sinv);
    dst[tid + 256] = __float2bfloat16(v1 * sinv);
}

// ---------------- kernel: transpose g_mnormb [J,C] -> g_mnormTb [C,J] ----------------
__global__ void transpose_m_kernel() {
    __shared__ __nv_bfloat16 t[32][34];
    int j0 = blockIdx.x * 32, c0 = blockIdx.y * 32;
    int lx = threadIdx.x, ly = threadIdx.y;   // 32 x 8
    #pragma unroll
    for (int ry = 0; ry < 32; ry += 8)
        t[ly + ry][lx] = g_mnormb[(size_t)(j0 + ly + ry) * CDIM + c0 + lx];
    __syncthreads();
    #pragma unroll
    for (int ry = 0; ry < 32; ry += 8)
        g_mnormTb[(size_t)(c0 + ly + ry) * MEMP + j0 + lx] = t[lx][ly + ry];
}

// ================ scores kernel: e = exp(q @ mnorm^T) -> att (fp32), Z sums ==================
// 128 tok x 128 mem tile, K=512, BK=32 elems (16 stages), cp.async double buffered
__global__ __launch_bounds__(256, 2) void attn_scores_mma(float* __restrict__ att) {
    extern __shared__ float dsm[];
    float* bufA[2] = { dsm,        dsm + 2560 };
    float* bufB[2] = { dsm + 5120, dsm + 7680 };

    const int j0 = blockIdx.x * 128;
    const int t0 = blockIdx.y * 128;

    __shared__ float zsum[128];

    const int tid = threadIdx.x;
    const int lane = tid & 31, wid = tid >> 5;
    const int wm = wid & 1, wn = wid >> 1;
    const int g = lane >> 2, tg = lane & 3;

    if (tid < 128) zsum[tid] = 0.0f;

    uint32_t aA[2], aB[2];
    aA[0] = (uint32_t)__cvta_generic_to_shared(bufA[0]);
    aA[1] = (uint32_t)__cvta_generic_to_shared(bufA[1]);
    aB[0] = (uint32_t)__cvta_generic_to_shared(bufB[0]);
    aB[1] = (uint32_t)__cvta_generic_to_shared(bufB[1]);

    const int r_ld = tid >> 2, q_ld = tid & 3;

    // prologue: stage 0
    #pragma unroll
    for (int i = 0; i < 2; i++) {
        int r = r_ld + i * 64;
        uint32_t doff = (uint32_t)(r * WSTRIDE + q_ld * 4) * 4;
        cp16(aA[0] + doff, &g_qb[(size_t)(t0 + r) * CDIM + q_ld * 8]);
        cp16(aB[0] + doff, &g_mnormb[(size_t)(j0 + r) * CDIM + q_ld * 8]);
    }
    CP_COMMIT();

    float acc[4][4][4] = {};

    #pragma unroll 1
    for (int it = 0; it < 16; ++it) {
        if (it + 1 < 16) {
            int nb = (it + 1) & 1;
            int k0 = (it + 1) * 32;
            #pragma unroll
            for (int i = 0; i < 2; i++) {
                int r = r_ld + i * 64;
                uint32_t doff = (uint32_t)(r * WSTRIDE + q_ld * 4) * 4;
                cp16(aA[nb] + doff, &g_qb[(size_t)(t0 + r) * CDIM + k0 + q_ld * 8]);
                cp16(aB[nb] + doff, &g_mnormb[(size_t)(j0 + r) * CDIM + k0 + q_ld * 8]);
            }
            CP_COMMIT();
            CP_WAIT1();
        } else {
            CP_WAIT0();
        }
        __syncthreads();

        const uint32_t* As = (const uint32_t*)bufA[it & 1];
        const uint32_t* Bs = (const uint32_t*)bufB[it & 1];
        #pragma unroll
        for (int kh = 0; kh < 2; kh++) {
            int ko = kh * 8;
            uint32_t a[4][4], b[4][2];
            #pragma unroll
            for (int i = 0; i < 4; i++) {
                const uint32_t* ap = &As[(wm * 64 + i * 16 + g) * WSTRIDE + ko + tg];
                a[i][0] = ap[0];
                a[i][1] = ap[8 * WSTRIDE];
                a[i][2] = ap[4];
                a[i][3] = ap[8 * WSTRIDE + 4];
            }
            #pragma unroll
            for (int j = 0; j < 4; j++) {
                const uint32_t* bp = &Bs[(wn * 32 + j * 8 + g) * WSTRIDE + ko + tg];
                b[j][0] = bp[0];
                b[j][1] = bp[4];
            }
            #pragma unroll
            for (int i = 0; i < 4; i++)
                #pragma unroll
                for (int j = 0; j < 4; j++)
                    MMA_BF16(acc[i][j], a[i], b[j]);
        }
        __syncthreads();
    }

    // epilogue: e = exp(score) -> att, Z reduction
    const int n = t0 >> 10, hwb = t0 & 1023;
    #pragma unroll
    for (int i = 0; i < 4; i++) {
        int r0 = wm * 64 + i * 16 + g;
        float z0 = 0.0f, z1 = 0.0f;
        #pragma unroll
        for (int j = 0; j < 4; j++) {
            int cb = wn * 32 + j * 8 + 2 * tg;
            #pragma unroll
            for (int cc = 0; cc < 2; cc++) {
                int jj = j0 + cb + cc;
                if (jj < MEMN) {
                    float e0 = __expf(acc[i][j][cc]);
                    float e1 = __expf(acc[i][j][cc + 2]);
                    size_t base = ((size_t)(n * MEMN + jj)) << 10;
                    att[base + hwb + r0] = e0;
                    att[base + hwb + r0 + 8] = e1;
                    z0 += e0; z1 += e1;
                }
            }
        }
        z0 += __shfl_xor_sync(0xffffffffu, z0, 1);
        z0 += __shfl_xor_sync(0xffffffffu, z0, 2);
        z1 += __shfl_xor_sync(0xffffffffu, z1, 1);
        z1 += __shfl_xor_sync(0xffffffffu, z1, 2);
        if (tg == 0) {
            atomicAdd(&zsum[r0], z0);
            atomicAdd(&zsum[r0 + 8], z1);
        }
    }
    __syncthreads();
    if (tid < 128) atomicAdd(&g_Z[t0 + tid], zsum[tid]);
}

// ================ fused finalize: L1 + flags + att_r in place ==================
// One block per 128-token tile. Pass 1 streams e from DRAM (L1 + activity flags);
// pass 2 re-reads the block's ~1MB e slice (L2-resident) and writes att_r in place.
__global__ __launch_bounds__(256) void finalize_fused_kernel(float* __restrict__ att) {
    const int t0 = blockIdx.x * 128;
    const int n = t0 >> 10, hw0 = t0 & 1023;
    const int tid = threadIdx.x;
    const int tok = tid & 127, jh = tid >> 7;

    __shared__ float zinv_s[128];
    __shared__ float l1p[256];
    __shared__ float l1inv_s[128];

    if (tid < 128) zinv_s[tid] = 1.0f / g_Z[t0 + tid];
    __syncthreads();

    const float ziv = zinv_s[tok];
    float* ebase = att + (((size_t)n * MEMN) << 10) + hw0 + tok;

    // pass 1: L1 + flags
    float l1 = 0.0f;
    #pragma unroll 1
    for (int st = 0; st < 64; st++) {
        int jb = st * 32 + jh * 16;
        int flag = 0;
        #pragma unroll
        for (int i = 0; i < 16; i++) {
            int j = jb + i;
            float e = (j < MEMN) ? ebase[(size_t)j << 10] : 0.0f;
            float p = fmaxf(e * ziv - SHRINK, 0.0f);
            l1 += p;
            flag |= (p > 0.0f);
        }
        int act = __syncthreads_or(flag);
        if (tid == 0) g_flags[blockIdx.x * 64 + st] = act;
    }

    l1p[tid] = l1;
    __syncthreads();
    if (tid < 128) l1inv_s[tid] = 1.0f / fmaxf(l1p[tid] + l1p[tid + 128], EPSV);
    __syncthreads();
    const float l1i = l1inv_s[tok];

    // pass 2: att_r = relu(e/Z - SHRINK) / max(L1, eps), in place (L2-hit reads)
    #pragma unroll 1
    for (int st = 0; st < 64; st++) {
        int jb = st * 32 + jh * 16;
        #pragma unroll
        for (int i = 0; i < 16; i++) {
            int j = jb + i;
            if (j < MEMN) {
                float e = ebase[(size_t)j << 10];
                ebase[(size_t)j << 10] = fmaxf(e * ziv - SHRINK, 0.0f) * l1i;
            }
        }
    }
}

// ================ out kernel: out = att_r @ mnorm, flag-gated stages ==================
// 128 tok x 128 chan tile, K=2048 mems, BK=32 (64 stages); A = finalized att_r (bf16)
__global__ __launch_bounds__(256, 2) void attn_out_mma(const float* __restrict__ att,
                                                       float* __restrict__ out) {
    extern __shared__ float dsm[];
    float* sA = dsm;                       // [128 tok][20 words] bf16 A-tile
    float* bufB[2] = { dsm + 2560, dsm + 5120 };

    const int c0b = blockIdx.x * 128;
    const int t0 = blockIdx.y * 128;
    const int n = t0 >> 10, hw0 = t0 & 1023;

    __shared__ int sflags[64];

    const int tid = threadIdx.x;
    const int lane = tid & 31, wid = tid >> 5;
    const int wm = wid & 1, wn = wid >> 1;
    const int g = lane >> 2, tg = lane & 3;

    if (tid < 64) sflags[tid] = g_flags[blockIdx.y * 64 + tid];
    __syncthreads();

    const int tok = tid & 127, jh = tid >> 7;
    const float* ebase = att + (((size_t)n * MEMN) << 10) + hw0 + tok;

    uint32_t aB[2];
    aB[0] = (uint32_t)__cvta_generic_to_shared(bufB[0]);
    aB[1] = (uint32_t)__cvta_generic_to_shared(bufB[1]);
    const int r_ld = tid >> 2, q_ld = tid & 3;

    float ar[16];
    uint32_t* sAw = (uint32_t*)sA;

    // prologue: stage 0 (only if active)
    if (sflags[0]) {
        #pragma unroll
        for (int i = 0; i < 16; i++) {
            int j = jh * 16 + i;
            ar[i] = (j < MEMN) ? ebase[(size_t)j << 10] : 0.0f;
        }
        #pragma unroll
        for (int i = 0; i < 2; i++) {
            int r = r_ld + i * 64;
            uint32_t doff = (uint32_t)(r * WSTRIDE + q_ld * 4) * 4;
            cp16(aB[0] + doff, &g_mnormTb[(size_t)(c0b + r) * MEMP + q_ld * 8]);
        }
    }
    CP_COMMIT();
    if (sflags[0]) {
        #pragma unroll
        for (int i = 0; i < 8; i++) {
            __nv_bfloat162 pk = __floats2bfloat162_rn(ar[2 * i], ar[2 * i + 1]);
            sAw[tok * WSTRIDE + jh * 8 + i] = *(uint32_t*)&pk;
        }
    }

    float acc[4][4][4] = {};

    #pragma unroll 1
    for (int it = 0; it < 64; ++it) {
        int nxt_active = 0;
        if (it + 1 < 64) {
            nxt_active = sflags[it + 1];
            if (nxt_active) {
                int nb = (it + 1) & 1;
                int k0 = (it + 1) * 32;
                #pragma unroll
                for (int i = 0; i < 2; i++) {
                    int r = r_ld + i * 64;
                    uint32_t doff = (uint32_t)(r * WSTRIDE + q_ld * 4) * 4;
                    cp16(aB[nb] + doff, &g_mnormTb[(size_t)(c0b + r) * MEMP + k0 + q_ld * 8]);
                }
            }
            CP_COMMIT();   // empty group when inactive — keeps group counting consistent
            if (nxt_active) {
                int k0 = (it + 1) * 32;
                #pragma unroll
                for (int i = 0; i < 16; i++) {
                    int j = k0 + jh * 16 + i;
                    ar[i] = (j < MEMN) ? ebase[(size_t)j << 10] : 0.0f;
                }
            }
            CP_WAIT1();
        } else {
            CP_WAIT0();
        }
        __syncthreads();   // sA stores + B(it) visible

        if (sflags[it]) {
            const uint32_t* Bs = (const uint32_t*)bufB[it & 1];
            #pragma unroll
            for (int kh = 0; kh < 2; kh++) {
                int ko = kh * 8;
                uint32_t a[4][4], b[4][2];
                #pragma unroll
                for (int i = 0; i < 4; i++) {
                    const uint32_t* ap = &sAw[(wm * 64 + i * 16 + g) * WSTRIDE + ko + tg];
                    a[i][0] = ap[0];
                    a[i][1] = ap[8 * WSTRIDE];
                    a[i][2] = ap[4];
                    a[i][3] = ap[8 * WSTRIDE + 4];
                }
                #pragma unroll
                for (int j = 0; j < 4; j++) {
                    const uint32_t* bp = &Bs[(wn * 32 + j * 8 + g) * WSTRIDE + ko + tg];
                    b[j][0] = bp[0];
                    b[j][1] = bp[4];
                }
                #pragma unroll
                for (int i = 0; i < 4; i++)
                    #pragma unroll
                    for (int j = 0; j < 4; j++)
                        MMA_BF16(acc[i][j], a[i], b[j]);
            }
        }
        __syncthreads();   // MMA reads of sA done before overwrite

        if (nxt_active) {
            #pragma unroll
            for (int i = 0; i < 8; i++) {
                __nv_bfloat162 pk = __floats2bfloat162_rn(ar[2 * i], ar[2 * i + 1]);
                sAw[tok * WSTRIDE + jh * 8 + i] = *(uint32_t*)&pk;
            }
        }
    }

    // epilogue: write out NCHW (no scaling — A was already att_r = p/L1)
    #pragma unroll
    for (int i = 0; i < 4; i++) {
        int r0 = wm * 64 + i * 16 + g;
        #pragma unroll
        for (int j = 0; j < 4; j++) {
            int cb = c0b + wn * 32 + j * 8 + 2 * tg;
            #pragma unroll
            for (int cc = 0; cc < 2; cc++) {
                size_t base = ((size_t)(n * CDIM + cb + cc)) << 10;
                out[base + hw0 + r0]     = acc[i][j][cc];
                out[base + hw0 + r0 + 8] = acc[i][j][cc + 2];
            }
        }
    }
}

// ---------------- launch ----------------
extern "C" void kernel_launch(void* const* d_in, const int* in_sizes, int n_in,
                              void* d_out, int out_size) {
    const float* x      = (const float*)d_in[0];
    const float* memory = (const float*)d_in[1];
    const float* w1     = (const float*)d_in[2];
    const float* b1     = (const float*)d_in[3];
    const float* w2     = (const float*)d_in[4];
    const float* b2     = (const float*)d_in[5];

    float* out = (float*)d_out;
    float* att = out + OUT_ELEMS;

    zero_z_kernel<<<TTOK / 256, 256>>>();
    build_q_kernel<<<NIMG * HDIM, 256>>>(x);
    mlp_gemm_kernel<<<dim3(CHID / 64, (MEMN + 63) / 64), 256>>>(memory, w1, b1, 0);
    mlp_gemm_kernel<<<dim3(CDIM / 64, (MEMN + 63) / 64), 256>>>(nullptr, w2, b2, 1);
    norm_rows_kernel<<<MEMP, 256>>>();
    transpose_m_kernel<<<dim3(MEMP / 32, CDIM / 32), dim3(32, 8)>>>();
    attn_scores_mma<<<dim3(MEMP / 128, TTOK / 128), 256, 40960>>>(att);
    finalize_fused_kernel<<<TTOK / 128, 256>>>(att);
    attn_out_mma<<<dim3(CDIM / 128, TTOK / 128), 256, 30720>>>(att, out);
}

// round 11
// speedup vs baseline: 1.1183x; 1.1183x over previous
#include <cuda_runtime.h>
#include <cuda_bf16.h>
#include <cstdint>
#include <math.h>

// ---------------- problem constants ----------------
#define NIMG 16
#define CDIM 512
#define HDIM 32
#define WDIM 32
#define TTOK (NIMG*HDIM*WDIM)      // 16384
#define MEMN 2000
#define MEMP 2048                   // padded
#define CHID 256
#define SHRINK 0.0025f
#define EPSV 1e-12f

#define OUT_ELEMS ((size_t)NIMG*CDIM*HDIM*WDIM)   // 8388608

// row stride for bf16 tiles: 40 halfs = 20 words (conflict-free fragment loads)
#define HSTRIDE 40
#define WSTRIDE 20

// ---------------- scratch (device globals) ----------------
__device__ __nv_bfloat16 g_qb[(size_t)TTOK * CDIM];       // bf16 queries [T,C]
__device__ float g_h[(size_t)MEMN * CHID];                 // MLP hidden (fp32)
__device__ float g_m[(size_t)MEMN * CDIM];                 // MLP out (pre-norm, fp32)
__device__ __nv_bfloat16 g_mnormb[(size_t)MEMP * CDIM];   // normalized memory [J,C] bf16, zero pad
__device__ __nv_bfloat16 g_mnormTb[(size_t)CDIM * MEMP];  // transposed [C,J] bf16, zero pad
__device__ float g_Z[TTOK];
__device__ float g_L1[TTOK];
__device__ int   g_flags[(TTOK / 128) * 64];               // per (token-tile, 32-mem stage) activity

#define MMA_BF16(c, a, b) \
    asm volatile("mma.sync.aligned.m16n8k16.row.col.f32.bf16.bf16.f32 " \
        "{%0,%1,%2,%3}, {%4,%5,%6,%7}, {%8,%9}, {%0,%1,%2,%3};" \
        : "+f"((c)[0]), "+f"((c)[1]), "+f"((c)[2]), "+f"((c)[3]) \
        : "r"((a)[0]), "r"((a)[1]), "r"((a)[2]), "r"((a)[3]), \
          "r"((b)[0]), "r"((b)[1]))

__device__ __forceinline__ void cp16(uint32_t dst, const void* src) {
    asm volatile("cp.async.ca.shared.global [%0], [%1], 16;" :: "r"(dst), "l"(src) : "memory");
}
#define CP_COMMIT() asm volatile("cp.async.commit_group;" ::: "memory")
#define CP_WAIT1()  asm volatile("cp.async.wait_group 1;" ::: "memory")
#define CP_WAIT0()  asm volatile("cp.async.wait_group 0;" ::: "memory")

// ---------------- kernel: zero Z ----------------
__global__ void zero_z_kernel() {
    int i = blockIdx.x * blockDim.x + threadIdx.x;
    if (i < TTOK) g_Z[i] = 0.0f;
}

// ---------------- kernel: build q (NCHW -> [T,C], L2 normalized, bf16) ----------------
__global__ void build_q_kernel(const float* __restrict__ x) {
    int bid = blockIdx.x;
    int n = bid >> 5, h = bid & 31;
    int tid = threadIdx.x;
    int w = tid & 31, cg = tid >> 5;

    __shared__ float ss[8][32];
    __shared__ float inv[32];
    __shared__ float xt[32][33];

    const float* xb = x + (size_t)n * (CDIM * HDIM * WDIM) + h * WDIM;

    float part = 0.0f;
    for (int c = cg; c < CDIM; c += 8) {
        float v = xb[c * 1024 + w];
        part += v * v;
    }
    ss[cg][w] = part;
    __syncthreads();
    if (tid < 32) {
        float s = 0.0f;
        #pragma unroll
        for (int g = 0; g < 8; g++) s += ss[g][tid];
        inv[tid] = 1.0f / fmaxf(sqrtf(s), EPSV);
    }
    __syncthreads();

    int t0 = n * 1024 + h * 32;
    int cl = tid & 31, tg = tid >> 5;
    for (int c0 = 0; c0 < CDIM; c0 += 32) {
        for (int ci = cg; ci < 32; ci += 8)
            xt[ci][w] = xb[(c0 + ci) * 1024 + w];
        __syncthreads();
        for (int tl = tg; tl < 32; tl += 8)
            g_qb[(size_t)(t0 + tl) * CDIM + c0 + cl] = __float2bfloat16(xt[cl][tl] * inv[tl]);
        __syncthreads();
    }
}

// ---------------- kernel: MLP GEMM  C = relu(A @ B^T + bias)  (SIMT fp32, R10-improved) ----------------
// transposed smem tiles [kk][row] (stride 68) -> inner loop uses 2x LDS.128 per kk
__global__ void mlp_gemm_kernel(const float* __restrict__ extA,
                                const float* __restrict__ Bw,
                                const float* __restrict__ bias,
                                int layer) {
    const float* A = layer ? (const float*)g_h : extA;
    float* Cc      = layer ? g_m : g_h;
    const int M = MEMN;
    const int N = layer ? CDIM : CHID;
    const int K = layer ? CHID : CDIM;

    int n0 = blockIdx.x * 64;
    int m0 = blockIdx.y * 64;

    __shared__ float As[32][68];
    __shared__ float Bs[32][68];

    int tid = threadIdx.x;
    int tx = tid & 15, ty = tid >> 4;
    float acc[4][4] = {};

    for (int k0 = 0; k0 < K; k0 += 32) {
        for (int idx = tid; idx < 512; idx += 256) {
            int r = idx >> 3, kq = (idx & 7) << 2;
            float4 v = make_float4(0.f, 0.f, 0.f, 0.f);
            if (m0 + r < M) v = *(const float4*)&A[(size_t)(m0 + r) * K + k0 + kq];
            As[kq + 0][r] = v.x; As[kq + 1][r] = v.y; As[kq + 2][r] = v.z; As[kq + 3][r] = v.w;
            float4 w = *(const float4*)&Bw[(size_t)(n0 + r) * K + k0 + kq];
            Bs[kq + 0][r] = w.x; Bs[kq + 1][r] = w.y; Bs[kq + 2][r] = w.z; Bs[kq + 3][r] = w.w;
        }
        __syncthreads();
        #pragma unroll
        for (int kk = 0; kk < 32; kk++) {
            float a[4], b[4];
            *(float4*)a = *(const float4*)&As[kk][tx * 4];
            *(float4*)b = *(const float4*)&Bs[kk][ty * 4];
            #pragma unroll
            for (int i = 0; i < 4; i++)
                #pragma unroll
                for (int j = 0; j < 4; j++)
                    acc[i][j] += a[i] * b[j];
        }
        __syncthreads();
    }

    #pragma unroll
    for (int j = 0; j < 4; j++) {
        int col = n0 + ty * 4 + j;
        float bv = bias[col];
        #pragma unroll
        for (int i = 0; i < 4; i++) {
            int row = m0 + tx * 4 + i;
            if (row < M) Cc[(size_t)row * N + col] = fmaxf(acc[i][j] + bv, 0.0f);
        }
    }
}

// ---------------- kernel: row L2-normalize m -> g_mnormb (bf16, zero pad) ----------------
__global__ void norm_rows_kernel() {
    int row = blockIdx.x;
    int tid = threadIdx.x;
    __nv_bfloat16* dst = &g_mnormb[(size_t)row * CDIM];
    if (row >= MEMN) {
        dst[tid] = __float2bfloat16(0.0f);
        dst[tid + 256] = __float2bfloat16(0.0f);
        return;
    }
    const float* src = &g_m[(size_t)row * CDIM];
    float v0 = src[tid], v1 = src[tid + 256];
    float ssv = v0 * v0 + v1 * v1;
    #pragma unroll
    for (int o = 16; o > 0; o >>= 1) ssv += __shfl_down_sync(0xffffffffu, ssv, o);
    __shared__ float red[8];
    __shared__ float sinv;
    if ((tid & 31) == 0) red[tid >> 5] = ssv;
    __syncthreads();
    if (tid == 0) {
        float s = 0.0f;
        #pragma unroll
        for (int i = 0; i < 8; i++) s += red[i];
        sinv = 1.0f / fmaxf(sqrtf(s), EPSV);
    }
    __syncthreads();
    dst[tid] = __float2bfloat16(v0 * sinv);
    dst[tid + 256] = __float2bfloat16(v1 * sinv);
}

// ---------------- kernel: transpose g_mnormb [J,C] -> g_mnormTb [C,J] ----------------
__global__ void transpose_m_kernel() {
    __shared__ __nv_bfloat16 t[32][34];
    int j0 = blockIdx.x * 32, c0 = blockIdx.y * 32;
    int lx = threadIdx.x, ly = threadIdx.y;   // 32 x 8
    #pragma unroll
    for (int ry = 0; ry < 32; ry += 8)
        t[ly + ry][lx] = g_mnormb[(size_t)(j0 + ly + ry) * CDIM + c0 + lx];
    __syncthreads();
    #pragma unroll
    for (int ry = 0; ry < 32; ry += 8)
        g_mnormTb[(size_t)(c0 + ly + ry) * MEMP + j0 + lx] = t[lx][ly + ry];
}

// ================ scores kernel: e = exp(q @ mnorm^T) -> att (fp32), Z sums ==================
// 128 tok x 128 mem tile, K=512, BK=32 elems (16 stages), cp.async double buffered
__global__ __launch_bounds__(256, 2) void attn_scores_mma(float* __restrict__ att) {
    extern __shared__ float dsm[];
    float* bufA[2] = { dsm,        dsm + 2560 };
    float* bufB[2] = { dsm + 5120, dsm + 7680 };

    const int j0 = blockIdx.x * 128;
    const int t0 = blockIdx.y * 128;

    __shared__ float zsum[128];

    const int tid = threadIdx.x;
    const int lane = tid & 31, wid = tid >> 5;
    const int wm = wid & 1, wn = wid >> 1;
    const int g = lane >> 2, tg = lane & 3;

    if (tid < 128) zsum[tid] = 0.0f;

    uint32_t aA[2], aB[2];
    aA[0] = (uint32_t)__cvta_generic_to_shared(bufA[0]);
    aA[1] = (uint32_t)__cvta_generic_to_shared(bufA[1]);
    aB[0] = (uint32_t)__cvta_generic_to_shared(bufB[0]);
    aB[1] = (uint32_t)__cvta_generic_to_shared(bufB[1]);

    const int r_ld = tid >> 2, q_ld = tid & 3;

    // prologue: stage 0
    #pragma unroll
    for (int i = 0; i < 2; i++) {
        int r = r_ld + i * 64;
        uint32_t doff = (uint32_t)(r * WSTRIDE + q_ld * 4) * 4;
        cp16(aA[0] + doff, &g_qb[(size_t)(t0 + r) * CDIM + q_ld * 8]);
        cp16(aB[0] + doff, &g_mnormb[(size_t)(j0 + r) * CDIM + q_ld * 8]);
    }
    CP_COMMIT();

    float acc[4][4][4] = {};

    #pragma unroll 1
    for (int it = 0; it < 16; ++it) {
        if (it + 1 < 16) {
            int nb = (it + 1) & 1;
            int k0 = (it + 1) * 32;
            #pragma unroll
            for (int i = 0; i < 2; i++) {
                int r = r_ld + i * 64;
                uint32_t doff = (uint32_t)(r * WSTRIDE + q_ld * 4) * 4;
                cp16(aA[nb] + doff, &g_qb[(size_t)(t0 + r) * CDIM + k0 + q_ld * 8]);
                cp16(aB[nb] + doff, &g_mnormb[(size_t)(j0 + r) * CDIM + k0 + q_ld * 8]);
            }
            CP_COMMIT();
            CP_WAIT1();
        } else {
            CP_WAIT0();
        }
        __syncthreads();

        const uint32_t* As = (const uint32_t*)bufA[it & 1];
        const uint32_t* Bs = (const uint32_t*)bufB[it & 1];
        #pragma unroll
        for (int kh = 0; kh < 2; kh++) {
            int ko = kh * 8;
            uint32_t a[4][4], b[4][2];
            #pragma unroll
            for (int i = 0; i < 4; i++) {
                const uint32_t* ap = &As[(wm * 64 + i * 16 + g) * WSTRIDE + ko + tg];
                a[i][0] = ap[0];
                a[i][1] = ap[8 * WSTRIDE];
                a[i][2] = ap[4];
                a[i][3] = ap[8 * WSTRIDE + 4];
            }
            #pragma unroll
            for (int j = 0; j < 4; j++) {
                const uint32_t* bp = &Bs[(wn * 32 + j * 8 + g) * WSTRIDE + ko + tg];
                b[j][0] = bp[0];
                b[j][1] = bp[4];
            }
            #pragma unroll
            for (int i = 0; i < 4; i++)
                #pragma unroll
                for (int j = 0; j < 4; j++)
                    MMA_BF16(acc[i][j], a[i], b[j]);
        }
        __syncthreads();
    }

    // epilogue: e = exp(score) -> att, Z reduction
    const int n = t0 >> 10, hwb = t0 & 1023;
    #pragma unroll
    for (int i = 0; i < 4; i++) {
        int r0 = wm * 64 + i * 16 + g;
        float z0 = 0.0f, z1 = 0.0f;
        #pragma unroll
        for (int j = 0; j < 4; j++) {
            int cb = wn * 32 + j * 8 + 2 * tg;
            #pragma unroll
            for (int cc = 0; cc < 2; cc++) {
                int jj = j0 + cb + cc;
                if (jj < MEMN) {
                    float e0 = __expf(acc[i][j][cc]);
                    float e1 = __expf(acc[i][j][cc + 2]);
                    size_t base = ((size_t)(n * MEMN + jj)) << 10;
                    att[base + hwb + r0] = e0;
                    att[base + hwb + r0 + 8] = e1;
                    z0 += e0; z1 += e1;
                }
            }
        }
        z0 += __shfl_xor_sync(0xffffffffu, z0, 1);
        z0 += __shfl_xor_sync(0xffffffffu, z0, 2);
        z1 += __shfl_xor_sync(0xffffffffu, z1, 1);
        z1 += __shfl_xor_sync(0xffffffffu, z1, 2);
        if (tg == 0) {
            atomicAdd(&zsum[r0], z0);
            atomicAdd(&zsum[r0 + 8], z1);
        }
    }
    __syncthreads();
    if (tid < 128) atomicAdd(&g_Z[t0 + tid], zsum[tid]);
}

// ================ l1 + activity flags kernel ==================
__global__ __launch_bounds__(256) void l1_flags_kernel(const float* __restrict__ att) {
    const int t0 = blockIdx.x * 128;
    const int n = t0 >> 10, hw0 = t0 & 1023;
    const int tid = threadIdx.x;
    const int tok = tid & 127, jh = tid >> 7;

    __shared__ float zinv_s[128];
    __shared__ float l1p[256];

    if (tid < 128) zinv_s[tid] = 1.0f / g_Z[t0 + tid];
    __syncthreads();

    const float ziv = zinv_s[tok];
    const float* ebase = att + (((size_t)n * MEMN) << 10) + hw0 + tok;

    float l1 = 0.0f;
    #pragma unroll 1
    for (int st = 0; st < 64; st++) {
        int jb = st * 32 + jh * 16;
        int flag = 0;
        #pragma unroll
        for (int i = 0; i < 16; i++) {
            int j = jb + i;
            float e = (j < MEMN) ? ebase[(size_t)j << 10] : 0.0f;
            float p = fmaxf(e * ziv - SHRINK, 0.0f);
            l1 += p;
            flag |= (p > 0.0f);
        }
        int act = __syncthreads_or(flag);
        if (tid == 0) g_flags[blockIdx.x * 64 + st] = act;
    }

    l1p[tid] = l1;
    __syncthreads();
    if (tid < 128) g_L1[t0 + tid] = l1p[tid] + l1p[tid + 128];
}

// ================ out kernel: out = (p @ mnorm)/L1, flag-gated stages ==================
__global__ __launch_bounds__(256, 2) void attn_out_mma(const float* __restrict__ att,
                                                       float* __restrict__ out) {
    extern __shared__ float dsm[];
    float* sA = dsm;                       // [128 tok][20 words] bf16 p-tile
    float* bufB[2] = { dsm + 2560, dsm + 5120 };

    const int c0b = blockIdx.x * 128;
    const int t0 = blockIdx.y * 128;
    const int n = t0 >> 10, hw0 = t0 & 1023;

    __shared__ float zinv_s[128];
    __shared__ float l1inv[128];
    __shared__ int sflags[64];

    const int tid = threadIdx.x;
    const int lane = tid & 31, wid = tid >> 5;
    const int wm = wid & 1, wn = wid >> 1;
    const int g = lane >> 2, tg = lane & 3;

    if (tid < 128) {
        zinv_s[tid] = 1.0f / g_Z[t0 + tid];
        l1inv[tid] = 1.0f / fmaxf(g_L1[t0 + tid], EPSV);
    }
    if (tid < 64) sflags[tid] = g_flags[blockIdx.y * 64 + tid];
    __syncthreads();

    const int tok = tid & 127, jh = tid >> 7;
    const float ziv = zinv_s[tok];
    const float* ebase = att + (((size_t)n * MEMN) << 10) + hw0 + tok;

    uint32_t aB[2];
    aB[0] = (uint32_t)__cvta_generic_to_shared(bufB[0]);
    aB[1] = (uint32_t)__cvta_generic_to_shared(bufB[1]);
    const int r_ld = tid >> 2, q_ld = tid & 3;

    float er[16];
    uint32_t* sAw = (uint32_t*)sA;

    // prologue: stage 0 (only if active)
    if (sflags[0]) {
        #pragma unroll
        for (int i = 0; i < 16; i++) {
            int j = jh * 16 + i;
            er[i] = (j < MEMN) ? ebase[(size_t)j << 10] : 0.0f;
        }
        #pragma unroll
        for (int i = 0; i < 2; i++) {
            int r = r_ld + i * 64;
            uint32_t doff = (uint32_t)(r * WSTRIDE + q_ld * 4) * 4;
            cp16(aB[0] + doff, &g_mnormTb[(size_t)(c0b + r) * MEMP + q_ld * 8]);
        }
    }
    CP_COMMIT();
    if (sflags[0]) {
        #pragma unroll
        for (int i = 0; i < 8; i++) {
            float p0 = fmaxf(er[2 * i] * ziv - SHRINK, 0.0f);
            float p1 = fmaxf(er[2 * i + 1] * ziv - SHRINK, 0.0f);
            __nv_bfloat162 pk = __floats2bfloat162_rn(p0, p1);
            sAw[tok * WSTRIDE + jh * 8 + i] = *(uint32_t*)&pk;
        }
    }

    float acc[4][4][4] = {};

    #pragma unroll 1
    for (int it = 0; it < 64; ++it) {
        int nxt_active = 0;
        if (it + 1 < 64) {
            nxt_active = sflags[it + 1];
            if (nxt_active) {
                int nb = (it + 1) & 1;
                int k0 = (it + 1) * 32;
                #pragma unroll
                for (int i = 0; i < 2; i++) {
                    int r = r_ld + i * 64;
                    uint32_t doff = (uint32_t)(r * WSTRIDE + q_ld * 4) * 4;
                    cp16(aB[nb] + doff, &g_mnormTb[(size_t)(c0b + r) * MEMP + k0 + q_ld * 8]);
                }
            }
            CP_COMMIT();   // empty group when inactive — keeps group counting consistent
            if (nxt_active) {
                int k0 = (it + 1) * 32;
                #pragma unroll
                for (int i = 0; i < 16; i++) {
                    int j = k0 + jh * 16 + i;
                    er[i] = (j < MEMN) ? ebase[(size_t)j << 10] : 0.0f;
                }
            }
            CP_WAIT1();
        } else {
            CP_WAIT0();
        }
        __syncthreads();   // sA stores + B(it) visible

        if (sflags[it]) {
            const uint32_t* Bs = (const uint32_t*)bufB[it & 1];
            #pragma unroll
            for (int kh = 0; kh < 2; kh++) {
                int ko = kh * 8;
                uint32_t a[4][4], b[4][2];
                #pragma unroll
                for (int i = 0; i < 4; i++) {
                    const uint32_t* ap = &sAw[(wm * 64 + i * 16 + g) * WSTRIDE + ko + tg];
                    a[i][0] = ap[0];
                    a[i][1] = ap[8 * WSTRIDE];
                    a[i][2] = ap[4];
                    a[i][3] = ap[8 * WSTRIDE + 4];
                }
                #pragma unroll
                for (int j = 0; j < 4; j++) {
                    const uint32_t* bp = &Bs[(wn * 32 + j * 8 + g) * WSTRIDE + ko + tg];
                    b[j][0] = bp[0];
                    b[j][1] = bp[4];
                }
                #pragma unroll
                for (int i = 0; i < 4; i++)
                    #pragma unroll
                    for (int j = 0; j < 4; j++)
                        MMA_BF16(acc[i][j], a[i], b[j]);
            }
        }
        __syncthreads();   // MMA reads of sA done before overwrite

        if (nxt_active) {
            #pragma unroll
            for (int i = 0; i < 8; i++) {
                float p0 = fmaxf(er[2 * i] * ziv - SHRINK, 0.0f);
                float p1 = fmaxf(er[2 * i + 1] * ziv - SHRINK, 0.0f);
                __nv_bfloat162 pk = __floats2bfloat162_rn(p0, p1);
                sAw[tok * WSTRIDE + jh * 8 + i] = *(uint32_t*)&pk;
            }
        }
    }

    // epilogue: write out NCHW scaled by 1/L1
    #pragma unroll
    for (int i = 0; i < 4; i++) {
        int r0 = wm * 64 + i * 16 + g;
        float li0 = l1inv[r0], li1 = l1inv[r0 + 8];
        #pragma unroll
        for (int j = 0; j < 4; j++) {
            int cb = c0b + wn * 32 + j * 8 + 2 * tg;
            #pragma unroll
            for (int cc = 0; cc < 2; cc++) {
                size_t base = ((size_t)(n * CDIM + cb + cc)) << 10;
                out[base + hw0 + r0]     = acc[i][j][cc]     * li0;
                out[base + hw0 + r0 + 8] = acc[i][j][cc + 2] * li1;
            }
        }
    }
}

// ---------------- finalize att_r = relu(e/Z - SHRINK)/max(L1,eps) in place ----------------
__global__ void att_finalize_kernel(float* __restrict__ att) {
    int b = blockIdx.x;
    int n = b / MEMN;
    int tid = threadIdx.x;
    size_t base = ((size_t)b << 10) + (tid << 2);
    int t = (n << 10) + (tid << 2);

    float4 e = *(float4*)&att[base];
    float4 z = *(const float4*)&g_Z[t];
    float4 l = *(const float4*)&g_L1[t];

    float4 r;
    r.x = fmaxf(e.x * (1.0f / z.x) - SHRINK, 0.0f) * (1.0f / fmaxf(l.x, EPSV));
    r.y = fmaxf(e.y * (1.0f / z.y) - SHRINK, 0.0f) * (1.0f / fmaxf(l.y, EPSV));
    r.z = fmaxf(e.z * (1.0f / z.z) - SHRINK, 0.0f) * (1.0f / fmaxf(l.z, EPSV));
    r.w = fmaxf(e.w * (1.0f / z.w) - SHRINK, 0.0f) * (1.0f / fmaxf(l.w, EPSV));
    *(float4*)&att[base] = r;
}

// ---------------- launch ----------------
extern "C" void kernel_launch(void* const* d_in, const int* in_sizes, int n_in,
                              void* d_out, int out_size) {
    const float* x      = (const float*)d_in[0];
    const float* memory = (const float*)d_in[1];
    const float* w1     = (const float*)d_in[2];
    const float* b1     = (const float*)d_in[3];
    const float* w2     = (const float*)d_in[4];
    const float* b2     = (const float*)d_in[5];

    float* out = (float*)d_out;
    float* att = out + OUT_ELEMS;

    zero_z_kernel<<<TTOK / 256, 256>>>();
    build_q_kernel<<<NIMG * HDIM, 256>>>(x);
    mlp_gemm_kernel<<<dim3(CHID / 64, (MEMN + 63) / 64), 256>>>(memory, w1, b1, 0);
    mlp_gemm_kernel<<<dim3(CDIM / 64, (MEMN + 63) / 64), 256>>>(nullptr, w2, b2, 1);
    norm_rows_kernel<<<MEMP, 256>>>();
    transpose_m_kernel<<<dim3(MEMP / 32, CDIM / 32), dim3(32, 8)>>>();
    attn_scores_mma<<<dim3(MEMP / 128, TTOK / 128), 256, 40960>>>(att);
    l1_flags_kernel<<<TTOK / 128, 256>>>(att);
    attn_out_mma<<<dim3(CDIM / 128, TTOK / 128), 256, 30720>>>(att, out);
    att_finalize_kernel<<<NIMG * MEMN, 256>>>(att);
}

// round 12
// speedup vs baseline: 1.2014x; 1.0742x over previous
#include <cuda_runtime.h>
#include <cuda_bf16.h>
#include <cstdint>
#include <math.h>

// ---------------- problem constants ----------------
#define NIMG 16
#define CDIM 512
#define HDIM 32
#define WDIM 32
#define TTOK (NIMG*HDIM*WDIM)      // 16384
#define MEMN 2000
#define MEMP 2048                   // padded
#define CHID 256
#define SHRINK 0.0025f
#define EPSV 1e-12f

#define OUT_ELEMS ((size_t)NIMG*CDIM*HDIM*WDIM)   // 8388608

// row strides (bf16 halfs / 32-bit words), conflict-free fragment loads
#define HSTRIDE 40
#define WSTRIDE 20
#define HSTRIDE64 72
#define WSTRIDE64 36

// ---------------- scratch (device globals) ----------------
__device__ __nv_bfloat16 g_qb[(size_t)TTOK * CDIM];       // bf16 queries [T,C]
__device__ float g_h[(size_t)MEMN * CHID];                 // MLP hidden (fp32)
__device__ float g_m[(size_t)MEMN * CDIM];                 // MLP out (pre-norm, fp32)
__device__ __nv_bfloat16 g_mnormb[(size_t)MEMP * CDIM];   // normalized memory [J,C] bf16, zero pad
__device__ __nv_bfloat16 g_mnormTb[(size_t)CDIM * MEMP];  // transposed [C,J] bf16, zero pad
__device__ float g_Z[TTOK];
__device__ float g_L1[TTOK];
__device__ int   g_flags[(TTOK / 128) * 64];               // per (token-tile, 32-mem stage) activity

#define MMA_BF16(c, a, b) \
    asm volatile("mma.sync.aligned.m16n8k16.row.col.f32.bf16.bf16.f32 " \
        "{%0,%1,%2,%3}, {%4,%5,%6,%7}, {%8,%9}, {%0,%1,%2,%3};" \
        : "+f"((c)[0]), "+f"((c)[1]), "+f"((c)[2]), "+f"((c)[3]) \
        : "r"((a)[0]), "r"((a)[1]), "r"((a)[2]), "r"((a)[3]), \
          "r"((b)[0]), "r"((b)[1]))

__device__ __forceinline__ void cp16(uint32_t dst, const void* src) {
    asm volatile("cp.async.ca.shared.global [%0], [%1], 16;" :: "r"(dst), "l"(src) : "memory");
}
#define CP_COMMIT() asm volatile("cp.async.commit_group;" ::: "memory")
#define CP_WAIT1()  asm volatile("cp.async.wait_group 1;" ::: "memory")
#define CP_WAIT0()  asm volatile("cp.async.wait_group 0;" ::: "memory")

// ---------------- kernel: zero Z ----------------
__global__ void zero_z_kernel() {
    int i = blockIdx.x * blockDim.x + threadIdx.x;
    if (i < TTOK) g_Z[i] = 0.0f;
}

// ---------------- kernel: build q (NCHW -> [T,C], L2 normalized, bf16) ----------------
__global__ void build_q_kernel(const float* __restrict__ x) {
    int bid = blockIdx.x;
    int n = bid >> 5, h = bid & 31;
    int tid = threadIdx.x;
    int w = tid & 31, cg = tid >> 5;

    __shared__ float ss[8][32];
    __shared__ float inv[32];
    __shared__ float xt[32][33];

    const float* xb = x + (size_t)n * (CDIM * HDIM * WDIM) + h * WDIM;

    float part = 0.0f;
    for (int c = cg; c < CDIM; c += 8) {
        float v = xb[c * 1024 + w];
        part += v * v;
    }
    ss[cg][w] = part;
    __syncthreads();
    if (tid < 32) {
        float s = 0.0f;
        #pragma unroll
        for (int g = 0; g < 8; g++) s += ss[g][tid];
        inv[tid] = 1.0f / fmaxf(sqrtf(s), EPSV);
    }
    __syncthreads();

    int t0 = n * 1024 + h * 32;
    int cl = tid & 31, tg = tid >> 5;
    for (int c0 = 0; c0 < CDIM; c0 += 32) {
        for (int ci = cg; ci < 32; ci += 8)
            xt[ci][w] = xb[(c0 + ci) * 1024 + w];
        __syncthreads();
        for (int tl = tg; tl < 32; tl += 8)
            g_qb[(size_t)(t0 + tl) * CDIM + c0 + cl] = __float2bfloat16(xt[cl][tl] * inv[tl]);
        __syncthreads();
    }
}

// ---------------- kernel: MLP GEMM  C = relu(A @ B^T + bias)  (SIMT fp32, R10-improved) ----------------
__global__ void mlp_gemm_kernel(const float* __restrict__ extA,
                                const float* __restrict__ Bw,
                                const float* __restrict__ bias,
                                int layer) {
    const float* A = layer ? (const float*)g_h : extA;
    float* Cc      = layer ? g_m : g_h;
    const int M = MEMN;
    const int N = layer ? CDIM : CHID;
    const int K = layer ? CHID : CDIM;

    int n0 = blockIdx.x * 64;
    int m0 = blockIdx.y * 64;

    __shared__ float As[32][68];
    __shared__ float Bs[32][68];

    int tid = threadIdx.x;
    int tx = tid & 15, ty = tid >> 4;
    float acc[4][4] = {};

    for (int k0 = 0; k0 < K; k0 += 32) {
        for (int idx = tid; idx < 512; idx += 256) {
            int r = idx >> 3, kq = (idx & 7) << 2;
            float4 v = make_float4(0.f, 0.f, 0.f, 0.f);
            if (m0 + r < M) v = *(const float4*)&A[(size_t)(m0 + r) * K + k0 + kq];
            As[kq + 0][r] = v.x; As[kq + 1][r] = v.y; As[kq + 2][r] = v.z; As[kq + 3][r] = v.w;
            float4 w = *(const float4*)&Bw[(size_t)(n0 + r) * K + k0 + kq];
            Bs[kq + 0][r] = w.x; Bs[kq + 1][r] = w.y; Bs[kq + 2][r] = w.z; Bs[kq + 3][r] = w.w;
        }
        __syncthreads();
        #pragma unroll
        for (int kk = 0; kk < 32; kk++) {
            float a[4], b[4];
            *(float4*)a = *(const float4*)&As[kk][tx * 4];
            *(float4*)b = *(const float4*)&Bs[kk][ty * 4];
            #pragma unroll
            for (int i = 0; i < 4; i++)
                #pragma unroll
                for (int j = 0; j < 4; j++)
                    acc[i][j] += a[i] * b[j];
        }
        __syncthreads();
    }

    #pragma unroll
    for (int j = 0; j < 4; j++) {
        int col = n0 + ty * 4 + j;
        float bv = bias[col];
        #pragma unroll
        for (int i = 0; i < 4; i++) {
            int row = m0 + tx * 4 + i;
            if (row < M) Cc[(size_t)row * N + col] = fmaxf(acc[i][j] + bv, 0.0f);
        }
    }
}

// ---------------- kernel: row L2-normalize m -> g_mnormb (bf16, zero pad) ----------------
__global__ void norm_rows_kernel() {
    int row = blockIdx.x;
    int tid = threadIdx.x;
    __nv_bfloat16* dst = &g_mnormb[(size_t)row * CDIM];
    if (row >= MEMN) {
        dst[tid] = __float2bfloat16(0.0f);
        dst[tid + 256] = __float2bfloat16(0.0f);
        return;
    }
    const float* src = &g_m[(size_t)row * CDIM];
    float v0 = src[tid], v1 = src[tid + 256];
    float ssv = v0 * v0 + v1 * v1;
    #pragma unroll
    for (int o = 16; o > 0; o >>= 1) ssv += __shfl_down_sync(0xffffffffu, ssv, o);
    __shared__ float red[8];
    __shared__ float sinv;
    if ((tid & 31) == 0) red[tid >> 5] = ssv;
    __syncthreads();
    if (tid == 0) {
        float s = 0.0f;
        #pragma unroll
        for (int i = 0; i < 8; i++) s += red[i];
        sinv = 1.0f / fmaxf(sqrtf(s), EPSV);
    }
    __syncthreads();
    dst[tid] = __float2bfloat16(v0 * sinv);
    dst[tid + 256] = __float2bfloat16(v1 * sinv);
}

// ---------------- kernel: transpose g_mnormb [J,C] -> g_mnormTb [C,J] ----------------
__global__ void transpose_m_kernel() {
    __shared__ __nv_bfloat16 t[32][34];
    int j0 = blockIdx.x * 32, c0 = blockIdx.y * 32;
    int lx = threadIdx.x, ly = threadIdx.y;   // 32 x 8
    #pragma unroll
    for (int ry = 0; ry < 32; ry += 8)
        t[ly + ry][lx] = g_mnormb[(size_t)(j0 + ly + ry) * CDIM + c0 + lx];
    __syncthreads();
    #pragma unroll
    for (int ry = 0; ry < 32; ry += 8)
        g_mnormTb[(size_t)(c0 + ly + ry) * MEMP + j0 + lx] = t[lx][ly + ry];
}

// ================ scores kernel: e = exp(q @ mnorm^T) -> att (fp32), Z sums ==================
// 128 tok x 128 mem tile, K=512, BK=64 elems (8 stages), cp.async double buffered
// dynamic smem: A0,A1,B0,B1 each 128 x 36 words = 18432 words = 73728 bytes
__global__ __launch_bounds__(256, 2) void attn_scores_mma(float* __restrict__ att) {
    extern __shared__ float dsm[];
    float* bufA[2] = { dsm,        dsm + 4608 };
    float* bufB[2] = { dsm + 9216, dsm + 13824 };

    const int j0 = blockIdx.x * 128;
    const int t0 = blockIdx.y * 128;

    __shared__ float zsum[128];

    const int tid = threadIdx.x;
    const int lane = tid & 31, wid = tid >> 5;
    const int wm = wid & 1, wn = wid >> 1;
    const int g = lane >> 2, tg = lane & 3;

    if (tid < 128) zsum[tid] = 0.0f;

    uint32_t aA[2], aB[2];
    aA[0] = (uint32_t)__cvta_generic_to_shared(bufA[0]);
    aA[1] = (uint32_t)__cvta_generic_to_shared(bufA[1]);
    aB[0] = (uint32_t)__cvta_generic_to_shared(bufB[0]);
    aB[1] = (uint32_t)__cvta_generic_to_shared(bufB[1]);

    // loaders: 1024 chunks of 16B per tile per stage (128 rows x 8 chunks); 4 per thread
    const int r_ld = tid >> 3, q_ld = tid & 7;

    // prologue: stage 0
    #pragma unroll
    for (int i = 0; i < 4; i++) {
        int r = r_ld + i * 32;
        uint32_t doff = (uint32_t)(r * WSTRIDE64 + q_ld * 4) * 4;
        cp16(aA[0] + doff, &g_qb[(size_t)(t0 + r) * CDIM + q_ld * 8]);
        cp16(aB[0] + doff, &g_mnormb[(size_t)(j0 + r) * CDIM + q_ld * 8]);
    }
    CP_COMMIT();

    float acc[4][4][4] = {};

    #pragma unroll 1
    for (int it = 0; it < 8; ++it) {
        if (it + 1 < 8) {
            int nb = (it + 1) & 1;
            int k0 = (it + 1) * 64;
            #pragma unroll
            for (int i = 0; i < 4; i++) {
                int r = r_ld + i * 32;
                uint32_t doff = (uint32_t)(r * WSTRIDE64 + q_ld * 4) * 4;
                cp16(aA[nb] + doff, &g_qb[(size_t)(t0 + r) * CDIM + k0 + q_ld * 8]);
                cp16(aB[nb] + doff, &g_mnormb[(size_t)(j0 + r) * CDIM + k0 + q_ld * 8]);
            }
            CP_COMMIT();
            CP_WAIT1();
        } else {
            CP_WAIT0();
        }
        __syncthreads();

        const uint32_t* As = (const uint32_t*)bufA[it & 1];
        const uint32_t* Bs = (const uint32_t*)bufB[it & 1];
        #pragma unroll
        for (int kh = 0; kh < 4; kh++) {
            int ko = kh * 8;
            uint32_t a[4][4], b[4][2];
            #pragma unroll
            for (int i = 0; i < 4; i++) {
                const uint32_t* ap = &As[(wm * 64 + i * 16 + g) * WSTRIDE64 + ko + tg];
                a[i][0] = ap[0];
                a[i][1] = ap[8 * WSTRIDE64];
                a[i][2] = ap[4];
                a[i][3] = ap[8 * WSTRIDE64 + 4];
            }
            #pragma unroll
            for (int j = 0; j < 4; j++) {
                const uint32_t* bp = &Bs[(wn * 32 + j * 8 + g) * WSTRIDE64 + ko + tg];
                b[j][0] = bp[0];
                b[j][1] = bp[4];
            }
            #pragma unroll
            for (int i = 0; i < 4; i++)
                #pragma unroll
                for (int j = 0; j < 4; j++)
                    MMA_BF16(acc[i][j], a[i], b[j]);
        }
        __syncthreads();
    }

    // epilogue: e = exp(score) -> att, Z reduction
    const int n = t0 >> 10, hwb = t0 & 1023;
    #pragma unroll
    for (int i = 0; i < 4; i++) {
        int r0 = wm * 64 + i * 16 + g;
        float z0 = 0.0f, z1 = 0.0f;
        #pragma unroll
        for (int j = 0; j < 4; j++) {
            int cb = wn * 32 + j * 8 + 2 * tg;
            #pragma unroll
            for (int cc = 0; cc < 2; cc++) {
                int jj = j0 + cb + cc;
                if (jj < MEMN) {
                    float e0 = __expf(acc[i][j][cc]);
                    float e1 = __expf(acc[i][j][cc + 2]);
                    size_t base = ((size_t)(n * MEMN + jj)) << 10;
                    att[base + hwb + r0] = e0;
                    att[base + hwb + r0 + 8] = e1;
                    z0 += e0; z1 += e1;
                }
            }
        }
        z0 += __shfl_xor_sync(0xffffffffu, z0, 1);
        z0 += __shfl_xor_sync(0xffffffffu, z0, 2);
        z1 += __shfl_xor_sync(0xffffffffu, z1, 1);
        z1 += __shfl_xor_sync(0xffffffffu, z1, 2);
        if (tg == 0) {
            atomicAdd(&zsum[r0], z0);
            atomicAdd(&zsum[r0 + 8], z1);
        }
    }
    __syncthreads();
    if (tid < 128) atomicAdd(&g_Z[t0 + tid], zsum[tid]);
}

// ================ l1 + activity flags kernel ==================
__global__ __launch_bounds__(256) void l1_flags_kernel(const float* __restrict__ att) {
    const int t0 = blockIdx.x * 128;
    const int n = t0 >> 10, hw0 = t0 & 1023;
    const int tid = threadIdx.x;
    const int tok = tid & 127, jh = tid >> 7;

    __shared__ float zinv_s[128];
    __shared__ float l1p[256];

    if (tid < 128) zinv_s[tid] = 1.0f / g_Z[t0 + tid];
    __syncthreads();

    const float ziv = zinv_s[tok];
    const float* ebase = att + (((size_t)n * MEMN) << 10) + hw0 + tok;

    float l1 = 0.0f;
    #pragma unroll 1
    for (int st = 0; st < 64; st++) {
        int jb = st * 32 + jh * 16;
        int flag = 0;
        #pragma unroll
        for (int i = 0; i < 16; i++) {
            int j = jb + i;
            float e = (j < MEMN) ? ebase[(size_t)j << 10] : 0.0f;
            float p = fmaxf(e * ziv - SHRINK, 0.0f);
            l1 += p;
            flag |= (p > 0.0f);
        }
        int act = __syncthreads_or(flag);
        if (tid == 0) g_flags[blockIdx.x * 64 + st] = act;
    }

    l1p[tid] = l1;
    __syncthreads();
    if (tid < 128) g_L1[t0 + tid] = l1p[tid] + l1p[tid + 128];
}

// ================ out kernel: out = (p @ mnorm)/L1, flag-gated stages ==================
__global__ __launch_bounds__(256, 2) void attn_out_mma(const float* __restrict__ att,
                                                       float* __restrict__ out) {
    extern __shared__ float dsm[];
    float* sA = dsm;                       // [128 tok][20 words] bf16 p-tile
    float* bufB[2] = { dsm + 2560, dsm + 5120 };

    const int c0b = blockIdx.x * 128;
    const int t0 = blockIdx.y * 128;
    const int n = t0 >> 10, hw0 = t0 & 1023;

    __shared__ float zinv_s[128];
    __shared__ float l1inv[128];
    __shared__ int sflags[64];

    const int tid = threadIdx.x;
    const int lane = tid & 31, wid = tid >> 5;
    const int wm = wid & 1, wn = wid >> 1;
    const int g = lane >> 2, tg = lane & 3;

    if (tid < 128) {
        zinv_s[tid] = 1.0f / g_Z[t0 + tid];
        l1inv[tid] = 1.0f / fmaxf(g_L1[t0 + tid], EPSV);
    }
    if (tid < 64) sflags[tid] = g_flags[blockIdx.y * 64 + tid];
    __syncthreads();

    const int tok = tid & 127, jh = tid >> 7;
    const float ziv = zinv_s[tok];
    const float* ebase = att + (((size_t)n * MEMN) << 10) + hw0 + tok;

    uint32_t aB[2];
    aB[0] = (uint32_t)__cvta_generic_to_shared(bufB[0]);
    aB[1] = (uint32_t)__cvta_generic_to_shared(bufB[1]);
    const int r_ld = tid >> 2, q_ld = tid & 3;

    float er[16];
    uint32_t* sAw = (uint32_t*)sA;

    // prologue: stage 0 (only if active)
    if (sflags[0]) {
        #pragma unroll
        for (int i = 0; i < 16; i++) {
            int j = jh * 16 + i;
            er[i] = (j < MEMN) ? ebase[(size_t)j << 10] : 0.0f;
        }
        #pragma unroll
        for (int i = 0; i < 2; i++) {
            int r = r_ld + i * 64;
            uint32_t doff = (uint32_t)(r * WSTRIDE + q_ld * 4) * 4;
            cp16(aB[0] + doff, &g_mnormTb[(size_t)(c0b + r) * MEMP + q_ld * 8]);
        }
    }
    CP_COMMIT();
    if (sflags[0]) {
        #pragma unroll
        for (int i = 0; i < 8; i++) {
            float p0 = fmaxf(er[2 * i] * ziv - SHRINK, 0.0f);
            float p1 = fmaxf(er[2 * i + 1] * ziv - SHRINK, 0.0f);
            __nv_bfloat162 pk = __floats2bfloat162_rn(p0, p1);
            sAw[tok * WSTRIDE + jh * 8 + i] = *(uint32_t*)&pk;
        }
    }

    float acc[4][4][4] = {};

    #pragma unroll 1
    for (int it = 0; it < 64; ++it) {
        int nxt_active = 0;
        if (it + 1 < 64) {
            nxt_active = sflags[it + 1];
            if (nxt_active) {
                int nb = (it + 1) & 1;
                int k0 = (it + 1) * 32;
                #pragma unroll
                for (int i = 0; i < 2; i++) {
                    int r = r_ld + i * 64;
                    uint32_t doff = (uint32_t)(r * WSTRIDE + q_ld * 4) * 4;
                    cp16(aB[nb] + doff, &g_mnormTb[(size_t)(c0b + r) * MEMP + k0 + q_ld * 8]);
                }
            }
            CP_COMMIT();   // empty group when inactive — keeps group counting consistent
            if (nxt_active) {
                int k0 = (it + 1) * 32;
                #pragma unroll
                for (int i = 0; i < 16; i++) {
                    int j = k0 + jh * 16 + i;
                    er[i] = (j < MEMN) ? ebase[(size_t)j << 10] : 0.0f;
                }
            }
            CP_WAIT1();
        } else {
            CP_WAIT0();
        }
        __syncthreads();   // sA stores + B(it) visible

        if (sflags[it]) {
            const uint32_t* Bs = (const uint32_t*)bufB[it & 1];
            #pragma unroll
            for (int kh = 0; kh < 2; kh++) {
                int ko = kh * 8;
                uint32_t a[4][4], b[4][2];
                #pragma unroll
                for (int i = 0; i < 4; i++) {
                    const uint32_t* ap = &sAw[(wm * 64 + i * 16 + g) * WSTRIDE + ko + tg];
                    a[i][0] = ap[0];
                    a[i][1] = ap[8 * WSTRIDE];
                    a[i][2] = ap[4];
                    a[i][3] = ap[8 * WSTRIDE + 4];
                }
                #pragma unroll
                for (int j = 0; j < 4; j++) {
                    const uint32_t* bp = &Bs[(wn * 32 + j * 8 + g) * WSTRIDE + ko + tg];
                    b[j][0] = bp[0];
                    b[j][1] = bp[4];
                }
                #pragma unroll
                for (int i = 0; i < 4; i++)
                    #pragma unroll
                    for (int j = 0; j < 4; j++)
                        MMA_BF16(acc[i][j], a[i], b[j]);
            }
        }
        __syncthreads();   // MMA reads of sA done before overwrite

        if (nxt_active) {
            #pragma unroll
            for (int i = 0; i < 8; i++) {
                float p0 = fmaxf(er[2 * i] * ziv - SHRINK, 0.0f);
                float p1 = fmaxf(er[2 * i + 1] * ziv - SHRINK, 0.0f);
                __nv_bfloat162 pk = __floats2bfloat162_rn(p0, p1);
                sAw[tok * WSTRIDE + jh * 8 + i] = *(uint32_t*)&pk;
            }
        }
    }

    // epilogue: write out NCHW scaled by 1/L1
    #pragma unroll
    for (int i = 0; i < 4; i++) {
        int r0 = wm * 64 + i * 16 + g;
        float li0 = l1inv[r0], li1 = l1inv[r0 + 8];
        #pragma unroll
        for (int j = 0; j < 4; j++) {
            int cb = c0b + wn * 32 + j * 8 + 2 * tg;
            #pragma unroll
            for (int cc = 0; cc < 2; cc++) {
                size_t base = ((size_t)(n * CDIM + cb + cc)) << 10;
                out[base + hw0 + r0]     = acc[i][j][cc]     * li0;
                out[base + hw0 + r0 + 8] = acc[i][j][cc + 2] * li1;
            }
        }
    }
}

// ---------------- finalize att_r = relu(e/Z - SHRINK)/max(L1,eps) in place ----------------
__global__ void att_finalize_kernel(float* __restrict__ att) {
    int b = blockIdx.x;
    int n = b / MEMN;
    int tid = threadIdx.x;
    size_t base = ((size_t)b << 10) + (tid << 2);
    int t = (n << 10) + (tid << 2);

    float4 e = *(float4*)&att[base];
    float4 z = *(const float4*)&g_Z[t];
    float4 l = *(const float4*)&g_L1[t];

    float4 r;
    r.x = fmaxf(e.x * (1.0f / z.x) - SHRINK, 0.0f) * (1.0f / fmaxf(l.x, EPSV));
    r.y = fmaxf(e.y * (1.0f / z.y) - SHRINK, 0.0f) * (1.0f / fmaxf(l.y, EPSV));
    r.z = fmaxf(e.z * (1.0f / z.z) - SHRINK, 0.0f) * (1.0f / fmaxf(l.z, EPSV));
    r.w = fmaxf(e.w * (1.0f / z.w) - SHRINK, 0.0f) * (1.0f / fmaxf(l.w, EPSV));
    *(float4*)&att[base] = r;
}

// ---------------- launch ----------------
extern "C" void kernel_launch(void* const* d_in, const int* in_sizes, int n_in,
                              void* d_out, int out_size) {
    const float* x      = (const float*)d_in[0];
    const float* memory = (const float*)d_in[1];
    const float* w1     = (const float*)d_in[2];
    const float* b1     = (const float*)d_in[3];
    const float* w2     = (const float*)d_in[4];
    const float* b2     = (const float*)d_in[5];

    float* out = (float*)d_out;
    float* att = out + OUT_ELEMS;

    cudaFuncSetAttribute(attn_scores_mma, cudaFuncAttributeMaxDynamicSharedMemorySize, 73728);

    zero_z_kernel<<<TTOK / 256, 256>>>();
    build_q_kernel<<<NIMG * HDIM, 256>>>(x);
    mlp_gemm_kernel<<<dim3(CHID / 64, (MEMN + 63) / 64), 256>>>(memory, w1, b1, 0);
    mlp_gemm_kernel<<<dim3(CDIM / 64, (MEMN + 63) / 64), 256>>>(nullptr, w2, b2, 1);
    norm_rows_kernel<<<MEMP, 256>>>();
    transpose_m_kernel<<<dim3(MEMP / 32, CDIM / 32), dim3(32, 8)>>>();
    attn_scores_mma<<<dim3(MEMP / 128, TTOK / 128), 256, 73728>>>(att);
    l1_flags_kernel<<<TTOK / 128, 256>>>(att);
    attn_out_mma<<<dim3(CDIM / 128, TTOK / 128), 256, 30720>>>(att, out);
    att_finalize_kernel<<<NIMG * MEMN, 256>>>(att);
}

// round 13
// speedup vs baseline: 1.2964x; 1.0791x over previous
#include <cuda_runtime.h>
#include <cuda_bf16.h>
#include <cstdint>
#include <math.h>

// ---------------- problem constants ----------------
#define NIMG 16
#define CDIM 512
#define HDIM 32
#define WDIM 32
#define TTOK (NIMG*HDIM*WDIM)      // 16384
#define MEMN 2000
#define MEMP 2048                   // padded
#define CHID 256
#define SHRINK 0.0025f
#define EPSV 1e-12f

#define OUT_ELEMS ((size_t)NIMG*CDIM*HDIM*WDIM)   // 8388608

// row strides (bf16 halfs / 32-bit words), conflict-free fragment loads
#define HSTRIDE 40
#define WSTRIDE 20
#define HSTRIDE64 72
#define WSTRIDE64 36

// ---------------- scratch (device globals) ----------------
__device__ __nv_bfloat16 g_qb[(size_t)TTOK * CDIM];       // bf16 queries [T,C]
__device__ float g_h[(size_t)MEMN * CHID];                 // MLP hidden (fp32)
__device__ float g_m[(size_t)MEMN * CDIM];                 // MLP out (pre-norm, fp32)
__device__ __nv_bfloat16 g_mnormb[(size_t)MEMP * CDIM];   // normalized memory [J,C] bf16, zero pad
__device__ __nv_bfloat16 g_mnormTb[(size_t)CDIM * MEMP];  // transposed [C,J] bf16, zero pad
__device__ float g_Z[TTOK];
__device__ float g_L1[TTOK];
__device__ int   g_flags[(TTOK / 128) * 64];               // per (token-tile, 32-mem stage) activity

#define MMA_BF16(c, a, b) \
    asm volatile("mma.sync.aligned.m16n8k16.row.col.f32.bf16.bf16.f32 " \
        "{%0,%1,%2,%3}, {%4,%5,%6,%7}, {%8,%9}, {%0,%1,%2,%3};" \
        : "+f"((c)[0]), "+f"((c)[1]), "+f"((c)[2]), "+f"((c)[3]) \
        : "r"((a)[0]), "r"((a)[1]), "r"((a)[2]), "r"((a)[3]), \
          "r"((b)[0]), "r"((b)[1]))

#define LDMATRIX_X4(r0, r1, r2, r3, addr) \
    asm volatile("ldmatrix.sync.aligned.m8n8.x4.shared.b16 {%0,%1,%2,%3}, [%4];" \
        : "=r"(r0), "=r"(r1), "=r"(r2), "=r"(r3) : "r"(addr))

__device__ __forceinline__ void cp16(uint32_t dst, const void* src) {
    asm volatile("cp.async.ca.shared.global [%0], [%1], 16;" :: "r"(dst), "l"(src) : "memory");
}
#define CP_COMMIT() asm volatile("cp.async.commit_group;" ::: "memory")
#define CP_WAIT1()  asm volatile("cp.async.wait_group 1;" ::: "memory")
#define CP_WAIT0()  asm volatile("cp.async.wait_group 0;" ::: "memory")

// ---------------- kernel: zero Z ----------------
__global__ void zero_z_kernel() {
    int i = blockIdx.x * blockDim.x + threadIdx.x;
    if (i < TTOK) g_Z[i] = 0.0f;
}

// ---------------- kernel: build q (NCHW -> [T,C], L2 normalized, bf16) ----------------
__global__ void build_q_kernel(const float* __restrict__ x) {
    int bid = blockIdx.x;
    int n = bid >> 5, h = bid & 31;
    int tid = threadIdx.x;
    int w = tid & 31, cg = tid >> 5;

    __shared__ float ss[8][32];
    __shared__ float inv[32];
    __shared__ float xt[32][33];

    const float* xb = x + (size_t)n * (CDIM * HDIM * WDIM) + h * WDIM;

    float part = 0.0f;
    for (int c = cg; c < CDIM; c += 8) {
        float v = xb[c * 1024 + w];
        part += v * v;
    }
    ss[cg][w] = part;
    __syncthreads();
    if (tid < 32) {
        float s = 0.0f;
        #pragma unroll
        for (int g = 0; g < 8; g++) s += ss[g][tid];
        inv[tid] = 1.0f / fmaxf(sqrtf(s), EPSV);
    }
    __syncthreads();

    int t0 = n * 1024 + h * 32;
    int cl = tid & 31, tg = tid >> 5;
    for (int c0 = 0; c0 < CDIM; c0 += 32) {
        for (int ci = cg; ci < 32; ci += 8)
            xt[ci][w] = xb[(c0 + ci) * 1024 + w];
        __syncthreads();
        for (int tl = tg; tl < 32; tl += 8)
            g_qb[(size_t)(t0 + tl) * CDIM + c0 + cl] = __float2bfloat16(xt[cl][tl] * inv[tl]);
        __syncthreads();
    }
}

// ---------------- kernel: MLP GEMM  C = relu(A @ B^T + bias)  (SIMT fp32, R10-improved) ----------------
__global__ void mlp_gemm_kernel(const float* __restrict__ extA,
                                const float* __restrict__ Bw,
                                const float* __restrict__ bias,
                                int layer) {
    const float* A = layer ? (const float*)g_h : extA;
    float* Cc      = layer ? g_m : g_h;
    const int M = MEMN;
    const int N = layer ? CDIM : CHID;
    const int K = layer ? CHID : CDIM;

    int n0 = blockIdx.x * 64;
    int m0 = blockIdx.y * 64;

    __shared__ float As[32][68];
    __shared__ float Bs[32][68];

    int tid = threadIdx.x;
    int tx = tid & 15, ty = tid >> 4;
    float acc[4][4] = {};

    for (int k0 = 0; k0 < K; k0 += 32) {
        for (int idx = tid; idx < 512; idx += 256) {
            int r = idx >> 3, kq = (idx & 7) << 2;
            float4 v = make_float4(0.f, 0.f, 0.f, 0.f);
            if (m0 + r < M) v = *(const float4*)&A[(size_t)(m0 + r) * K + k0 + kq];
            As[kq + 0][r] = v.x; As[kq + 1][r] = v.y; As[kq + 2][r] = v.z; As[kq + 3][r] = v.w;
            float4 w = *(const float4*)&Bw[(size_t)(n0 + r) * K + k0 + kq];
            Bs[kq + 0][r] = w.x; Bs[kq + 1][r] = w.y; Bs[kq + 2][r] = w.z; Bs[kq + 3][r] = w.w;
        }
        __syncthreads();
        #pragma unroll
        for (int kk = 0; kk < 32; kk++) {
            float a[4], b[4];
            *(float4*)a = *(const float4*)&As[kk][tx * 4];
            *(float4*)b = *(const float4*)&Bs[kk][ty * 4];
            #pragma unroll
            for (int i = 0; i < 4; i++)
                #pragma unroll
                for (int j = 0; j < 4; j++)
                    acc[i][j] += a[i] * b[j];
        }
        __syncthreads();
    }

    #pragma unroll
    for (int j = 0; j < 4; j++) {
        int col = n0 + ty * 4 + j;
        float bv = bias[col];
        #pragma unroll
        for (int i = 0; i < 4; i++) {
            int row = m0 + tx * 4 + i;
            if (row < M) Cc[(size_t)row * N + col] = fmaxf(acc[i][j] + bv, 0.0f);
        }
    }
}

// ---------------- kernel: row L2-normalize m -> g_mnormb (bf16, zero pad) ----------------
__global__ void norm_rows_kernel() {
    int row = blockIdx.x;
    int tid = threadIdx.x;
    __nv_bfloat16* dst = &g_mnormb[(size_t)row * CDIM];
    if (row >= MEMN) {
        dst[tid] = __float2bfloat16(0.0f);
        dst[tid + 256] = __float2bfloat16(0.0f);
        return;
    }
    const float* src = &g_m[(size_t)row * CDIM];
    float v0 = src[tid], v1 = src[tid + 256];
    float ssv = v0 * v0 + v1 * v1;
    #pragma unroll
    for (int o = 16; o > 0; o >>= 1) ssv += __shfl_down_sync(0xffffffffu, ssv, o);
    __shared__ float red[8];
    __shared__ float sinv;
    if ((tid & 31) == 0) red[tid >> 5] = ssv;
    __syncthreads();
    if (tid == 0) {
        float s = 0.0f;
        #pragma unroll
        for (int i = 0; i < 8; i++) s += red[i];
        sinv = 1.0f / fmaxf(sqrtf(s), EPSV);
    }
    __syncthreads();
    dst[tid] = __float2bfloat16(v0 * sinv);
    dst[tid + 256] = __float2bfloat16(v1 * sinv);
}

// ---------------- kernel: transpose g_mnormb [J,C] -> g_mnormTb [C,J] ----------------
__global__ void transpose_m_kernel() {
    __shared__ __nv_bfloat16 t[32][34];
    int j0 = blockIdx.x * 32, c0 = blockIdx.y * 32;
    int lx = threadIdx.x, ly = threadIdx.y;   // 32 x 8
    #pragma unroll
    for (int ry = 0; ry < 32; ry += 8)
        t[ly + ry][lx] = g_mnormb[(size_t)(j0 + ly + ry) * CDIM + c0 + lx];
    __syncthreads();
    #pragma unroll
    for (int ry = 0; ry < 32; ry += 8)
        g_mnormTb[(size_t)(c0 + ly + ry) * MEMP + j0 + lx] = t[lx][ly + ry];
}

// ================ scores kernel: e = exp(q @ mnorm^T) -> att (fp32), Z sums ==================
// 128 tok x 128 mem tile, K=512, BK=64 elems (8 stages), cp.async double buffered
// fragment loads via ldmatrix.x4 (6 per k16-step instead of 24 LDS.32)
__global__ __launch_bounds__(256, 2) void attn_scores_mma(float* __restrict__ att) {
    extern __shared__ float dsm[];
    float* bufA[2] = { dsm,        dsm + 4608 };
    float* bufB[2] = { dsm + 9216, dsm + 13824 };

    const int j0 = blockIdx.x * 128;
    const int t0 = blockIdx.y * 128;

    __shared__ float zsum[128];

    const int tid = threadIdx.x;
    const int lane = tid & 31, wid = tid >> 5;
    const int wm = wid & 1, wn = wid >> 1;
    const int g = lane >> 2, tg = lane & 3;

    if (tid < 128) zsum[tid] = 0.0f;

    uint32_t aA[2], aB[2];
    aA[0] = (uint32_t)__cvta_generic_to_shared(bufA[0]);
    aA[1] = (uint32_t)__cvta_generic_to_shared(bufA[1]);
    aB[0] = (uint32_t)__cvta_generic_to_shared(bufB[0]);
    aB[1] = (uint32_t)__cvta_generic_to_shared(bufB[1]);

    // per-lane ldmatrix base byte-offsets (within a buffer)
    uint32_t aoff[4], boff[2];
    {
        int lr = lane & 15, lc = lane >> 4;       // A: rows 0-15, col-chunk 0/1
        #pragma unroll
        for (int i = 0; i < 4; i++)
            aoff[i] = (uint32_t)(((wm * 64 + i * 16 + lr) * WSTRIDE64 + lc * 4) * 4);
        int q = lane >> 3, r8 = lane & 7;         // B: quad q -> (j-sub, k-chunk)
        #pragma unroll
        for (int jp = 0; jp < 2; jp++) {
            int jrow = wn * 32 + (jp * 2 + (q >> 1)) * 8 + r8;
            boff[jp] = (uint32_t)((jrow * WSTRIDE64 + (q & 1) * 4) * 4);
        }
    }

    // loaders: 1024 chunks of 16B per tile per stage (128 rows x 8 chunks); 4 per thread
    const int r_ld = tid >> 3, q_ld = tid & 7;

    // prologue: stage 0
    #pragma unroll
    for (int i = 0; i < 4; i++) {
        int r = r_ld + i * 32;
        uint32_t doff = (uint32_t)(r * WSTRIDE64 + q_ld * 4) * 4;
        cp16(aA[0] + doff, &g_qb[(size_t)(t0 + r) * CDIM + q_ld * 8]);
        cp16(aB[0] + doff, &g_mnormb[(size_t)(j0 + r) * CDIM + q_ld * 8]);
    }
    CP_COMMIT();

    float acc[4][4][4] = {};

    #pragma unroll 1
    for (int it = 0; it < 8; ++it) {
        if (it + 1 < 8) {
            int nb = (it + 1) & 1;
            int k0 = (it + 1) * 64;
            #pragma unroll
            for (int i = 0; i < 4; i++) {
                int r = r_ld + i * 32;
                uint32_t doff = (uint32_t)(r * WSTRIDE64 + q_ld * 4) * 4;
                cp16(aA[nb] + doff, &g_qb[(size_t)(t0 + r) * CDIM + k0 + q_ld * 8]);
                cp16(aB[nb] + doff, &g_mnormb[(size_t)(j0 + r) * CDIM + k0 + q_ld * 8]);
            }
            CP_COMMIT();
            CP_WAIT1();
        } else {
            CP_WAIT0();
        }
        __syncthreads();

        const uint32_t Ab = aA[it & 1];
        const uint32_t Bb = aB[it & 1];
        #pragma unroll
        for (int kh = 0; kh < 4; kh++) {
            uint32_t kbyte = (uint32_t)(kh * 32);    // 8 words per k16 step
            uint32_t a[4][4], b[4][2];
            #pragma unroll
            for (int i = 0; i < 4; i++)
                LDMATRIX_X4(a[i][0], a[i][1], a[i][2], a[i][3], Ab + aoff[i] + kbyte);
            #pragma unroll
            for (int jp = 0; jp < 2; jp++)
                LDMATRIX_X4(b[jp * 2][0], b[jp * 2][1], b[jp * 2 + 1][0], b[jp * 2 + 1][1],
                            Bb + boff[jp] + kbyte);
            #pragma unroll
            for (int i = 0; i < 4; i++)
                #pragma unroll
                for (int j = 0; j < 4; j++)
                    MMA_BF16(acc[i][j], a[i], b[j]);
        }
        __syncthreads();
    }

    // epilogue: e = exp(score) -> att, Z reduction
    const int n = t0 >> 10, hwb = t0 & 1023;
    #pragma unroll
    for (int i = 0; i < 4; i++) {
        int r0 = wm * 64 + i * 16 + g;
        float z0 = 0.0f, z1 = 0.0f;
        #pragma unroll
        for (int j = 0; j < 4; j++) {
            int cb = wn * 32 + j * 8 + 2 * tg;
            #pragma unroll
            for (int cc = 0; cc < 2; cc++) {
                int jj = j0 + cb + cc;
                if (jj < MEMN) {
                    float e0 = __expf(acc[i][j][cc]);
                    float e1 = __expf(acc[i][j][cc + 2]);
                    size_t base = ((size_t)(n * MEMN + jj)) << 10;
                    att[base + hwb + r0] = e0;
                    att[base + hwb + r0 + 8] = e1;
                    z0 += e0; z1 += e1;
                }
            }
        }
        z0 += __shfl_xor_sync(0xffffffffu, z0, 1);
        z0 += __shfl_xor_sync(0xffffffffu, z0, 2);
        z1 += __shfl_xor_sync(0xffffffffu, z1, 1);
        z1 += __shfl_xor_sync(0xffffffffu, z1, 2);
        if (tg == 0) {
            atomicAdd(&zsum[r0], z0);
            atomicAdd(&zsum[r0 + 8], z1);
        }
    }
    __syncthreads();
    if (tid < 128) atomicAdd(&g_Z[t0 + tid], zsum[tid]);
}

// ================ l1 + activity flags kernel ==================
__global__ __launch_bounds__(256) void l1_flags_kernel(const float* __restrict__ att) {
    const int t0 = blockIdx.x * 128;
    const int n = t0 >> 10, hw0 = t0 & 1023;
    const int tid = threadIdx.x;
    const int tok = tid & 127, jh = tid >> 7;

    __shared__ float zinv_s[128];
    __shared__ float l1p[256];

    if (tid < 128) zinv_s[tid] = 1.0f / g_Z[t0 + tid];
    __syncthreads();

    const float ziv = zinv_s[tok];
    const float* ebase = att + (((size_t)n * MEMN) << 10) + hw0 + tok;

    float l1 = 0.0f;
    #pragma unroll 1
    for (int st = 0; st < 64; st++) {
        int jb = st * 32 + jh * 16;
        int flag = 0;
        #pragma unroll
        for (int i = 0; i < 16; i++) {
            int j = jb + i;
            float e = (j < MEMN) ? ebase[(size_t)j << 10] : 0.0f;
            float p = fmaxf(e * ziv - SHRINK, 0.0f);
            l1 += p;
            flag |= (p > 0.0f);
        }
        int act = __syncthreads_or(flag);
        if (tid == 0) g_flags[blockIdx.x * 64 + st] = act;
    }

    l1p[tid] = l1;
    __syncthreads();
    if (tid < 128) g_L1[t0 + tid] = l1p[tid] + l1p[tid + 128];
}

// ================ out kernel: out = (p @ mnorm)/L1, flag-gated stages ==================
__global__ __launch_bounds__(256, 2) void attn_out_mma(const float* __restrict__ att,
                                                       float* __restrict__ out) {
    extern __shared__ float dsm[];
    float* sA = dsm;                       // [128 tok][20 words] bf16 p-tile
    float* bufB[2] = { dsm + 2560, dsm + 5120 };

    const int c0b = blockIdx.x * 128;
    const int t0 = blockIdx.y * 128;
    const int n = t0 >> 10, hw0 = t0 & 1023;

    __shared__ float zinv_s[128];
    __shared__ float l1inv[128];
    __shared__ int sflags[64];

    const int tid = threadIdx.x;
    const int lane = tid & 31, wid = tid >> 5;
    const int wm = wid & 1, wn = wid >> 1;
    const int g = lane >> 2, tg = lane & 3;

    if (tid < 128) {
        zinv_s[tid] = 1.0f / g_Z[t0 + tid];
        l1inv[tid] = 1.0f / fmaxf(g_L1[t0 + tid], EPSV);
    }
    if (tid < 64) sflags[tid] = g_flags[blockIdx.y * 64 + tid];
    __syncthreads();

    const int tok = tid & 127, jh = tid >> 7;
    const float ziv = zinv_s[tok];
    const float* ebase = att + (((size_t)n * MEMN) << 10) + hw0 + tok;

    uint32_t aB[2];
    aB[0] = (uint32_t)__cvta_generic_to_shared(bufB[0]);
    aB[1] = (uint32_t)__cvta_generic_to_shared(bufB[1]);
    const int r_ld = tid >> 2, q_ld = tid & 3;

    float er[16];
    uint32_t* sAw = (uint32_t*)sA;

    // prologue: stage 0 (only if active)
    if (sflags[0]) {
        #pragma unroll
        for (int i = 0; i < 16; i++) {
            int j = jh * 16 + i;
            er[i] = (j < MEMN) ? ebase[(size_t)j << 10] : 0.0f;
        }
        #pragma unroll
        for (int i = 0; i < 2; i++) {
            int r = r_ld + i * 64;
            uint32_t doff = (uint32_t)(r * WSTRIDE + q_ld * 4) * 4;
            cp16(aB[0] + doff, &g_mnormTb[(size_t)(c0b + r) * MEMP + q_ld * 8]);
        }
    }
    CP_COMMIT();
    if (sflags[0]) {
        #pragma unroll
        for (int i = 0; i < 8; i++) {
            float p0 = fmaxf(er[2 * i] * ziv - SHRINK, 0.0f);
            float p1 = fmaxf(er[2 * i + 1] * ziv - SHRINK, 0.0f);
            __nv_bfloat162 pk = __floats2bfloat162_rn(p0, p1);
            sAw[tok * WSTRIDE + jh * 8 + i] = *(uint32_t*)&pk;
        }
    }

    float acc[4][4][4] = {};

    #pragma unroll 1
    for (int it = 0; it < 64; ++it) {
        int nxt_active = 0;
        if (it + 1 < 64) {
            nxt_active = sflags[it + 1];
            if (nxt_active) {
                int nb = (it + 1) & 1;
                int k0 = (it + 1) * 32;
                #pragma unroll
                for (int i = 0; i < 2; i++) {
                    int r = r_ld + i * 64;
                    uint32_t doff = (uint32_t)(r * WSTRIDE + q_ld * 4) * 4;
                    cp16(aB[nb] + doff, &g_mnormTb[(size_t)(c0b + r) * MEMP + k0 + q_ld * 8]);
                }
            }
            CP_COMMIT();   // empty group when inactive — keeps group counting consistent
            if (nxt_active) {
                int k0 = (it + 1) * 32;
                #pragma unroll
                for (int i = 0; i < 16; i++) {
                    int j = k0 + jh * 16 + i;
                    er[i] = (j < MEMN) ? ebase[(size_t)j << 10] : 0.0f;
                }
            }
            CP_WAIT1();
        } else {
            CP_WAIT0();
        }
        __syncthreads();   // sA stores + B(it) visible

        if (sflags[it]) {
            const uint32_t* Bs = (const uint32_t*)bufB[it & 1];
            #pragma unroll
            for (int kh = 0; kh < 2; kh++) {
                int ko = kh * 8;
                uint32_t a[4][4], b[4][2];
                #pragma unroll
                for (int i = 0; i < 4; i++) {
                    const uint32_t* ap = &sAw[(wm * 64 + i * 16 + g) * WSTRIDE + ko + tg];
                    a[i][0] = ap[0];
                    a[i][1] = ap[8 * WSTRIDE];
                    a[i][2] = ap[4];
                    a[i][3] = ap[8 * WSTRIDE + 4];
                }
                #pragma unroll
                for (int j = 0; j < 4; j++) {
                    const uint32_t* bp = &Bs[(wn * 32 + j * 8 + g) * WSTRIDE + ko + tg];
                    b[j][0] = bp[0];
                    b[j][1] = bp[4];
                }
                #pragma unroll
                for (int i = 0; i < 4; i++)
                    #pragma unroll
                    for (int j = 0; j < 4; j++)
                        MMA_BF16(acc[i][j], a[i], b[j]);
            }
        }
        __syncthreads();   // MMA reads of sA done before overwrite

        if (nxt_active) {
            #pragma unroll
            for (int i = 0; i < 8; i++) {
                float p0 = fmaxf(er[2 * i] * ziv - SHRINK, 0.0f);
                float p1 = fmaxf(er[2 * i + 1] * ziv - SHRINK, 0.0f);
                __nv_bfloat162 pk = __floats2bfloat162_rn(p0, p1);
                sAw[tok * WSTRIDE + jh * 8 + i] = *(uint32_t*)&pk;
            }
        }
    }

    // epilogue: write out NCHW scaled by 1/L1
    #pragma unroll
    for (int i = 0; i < 4; i++) {
        int r0 = wm * 64 + i * 16 + g;
        float li0 = l1inv[r0], li1 = l1inv[r0 + 8];
        #pragma unroll
        for (int j = 0; j < 4; j++) {
            int cb = c0b + wn * 32 + j * 8 + 2 * tg;
            #pragma unroll
            for (int cc = 0; cc < 2; cc++) {
                size_t base = ((size_t)(n * CDIM + cb + cc)) << 10;
                out[base + hw0 + r0]     = acc[i][j][cc]     * li0;
                out[base + hw0 + r0 + 8] = acc[i][j][cc + 2] * li1;
            }
        }
    }
}

// ---------------- finalize att_r = relu(e/Z - SHRINK)/max(L1,eps) in place ----------------
__global__ void att_finalize_kernel(float* __restrict__ att) {
    int b = blockIdx.x;
    int n = b / MEMN;
    int tid = threadIdx.x;
    size_t base = ((size_t)b << 10) + (tid << 2);
    int t = (n << 10) + (tid << 2);

    float4 e = *(float4*)&att[base];
    float4 z = *(const float4*)&g_Z[t];
    float4 l = *(const float4*)&g_L1[t];

    float4 r;
    r.x = fmaxf(e.x * (1.0f / z.x) - SHRINK, 0.0f) * (1.0f / fmaxf(l.x, EPSV));
    r.y = fmaxf(e.y * (1.0f / z.y) - SHRINK, 0.0f) * (1.0f / fmaxf(l.y, EPSV));
    r.z = fmaxf(e.z * (1.0f / z.z) - SHRINK, 0.0f) * (1.0f / fmaxf(l.z, EPSV));
    r.w = fmaxf(e.w * (1.0f / z.w) - SHRINK, 0.0f) * (1.0f / fmaxf(l.w, EPSV));
    *(float4*)&att[base] = r;
}

// ---------------- launch ----------------
extern "C" void kernel_launch(void* const* d_in, const int* in_sizes, int n_in,
                              void* d_out, int out_size) {
    const float* x      = (const float*)d_in[0];
    const float* memory = (const float*)d_in[1];
    const float* w1     = (const float*)d_in[2];
    const float* b1     = (const float*)d_in[3];
    const float* w2     = (const float*)d_in[4];
    const float* b2     = (const float*)d_in[5];

    float* out = (float*)d_out;
    float* att = out + OUT_ELEMS;

    cudaFuncSetAttribute(attn_scores_mma, cudaFuncAttributeMaxDynamicSharedMemorySize, 73728);

    zero_z_kernel<<<TTOK / 256, 256>>>();
    build_q_kernel<<<NIMG * HDIM, 256>>>(x);
    mlp_gemm_kernel<<<dim3(CHID / 64, (MEMN + 63) / 64), 256>>>(memory, w1, b1, 0);
    mlp_gemm_kernel<<<dim3(CDIM / 64, (MEMN + 63) / 64), 256>>>(nullptr, w2, b2, 1);
    norm_rows_kernel<<<MEMP, 256>>>();
    transpose_m_kernel<<<dim3(MEMP / 32, CDIM / 32), dim3(32, 8)>>>();
    attn_scores_mma<<<dim3(MEMP / 128, TTOK / 128), 256, 73728>>>(att);
    l1_flags_kernel<<<TTOK / 128, 256>>>(att);
    attn_out_mma<<<dim3(CDIM / 128, TTOK / 128), 256, 30720>>>(att, out);
    att_finalize_kernel<<<NIMG * MEMN, 256>>>(att);
}

// round 14
// speedup vs baseline: 1.3335x; 1.0286x over previous
#include <cuda_runtime.h>
#include <cuda_bf16.h>
#include <cstdint>
#include <math.h>

// ---------------- problem constants ----------------
#define NIMG 16
#define CDIM 512
#define HDIM 32
#define WDIM 32
#define TTOK (NIMG*HDIM*WDIM)      // 16384
#define MEMN 2000
#define MEMP 2048                   // padded
#define CHID 256
#define SHRINK 0.0025f
#define EPSV 1e-12f

#define OUT_ELEMS ((size_t)NIMG*CDIM*HDIM*WDIM)   // 8388608

// row strides (bf16 halfs / 32-bit words), conflict-free fragment loads
#define HSTRIDE 40
#define WSTRIDE 20
#define HSTRIDE64 72
#define WSTRIDE64 36

// ---------------- scratch (device globals) ----------------
__device__ __nv_bfloat16 g_qb[(size_t)TTOK * CDIM];       // bf16 queries [T,C]
__device__ float g_h[(size_t)MEMN * CHID];                 // MLP hidden (fp32)
__device__ float g_m[(size_t)MEMN * CDIM];                 // MLP out (pre-norm, fp32)
__device__ __nv_bfloat16 g_mnormb[(size_t)MEMP * CDIM];   // normalized memory [J,C] bf16, zero pad
__device__ __nv_bfloat16 g_mnormTb[(size_t)CDIM * MEMP];  // transposed [C,J] bf16, zero pad
__device__ float g_Z[TTOK];
__device__ float g_L1[TTOK];
__device__ int   g_flags[(TTOK / 128) * 64];               // per (token-tile, 32-mem stage) activity

#define MMA_BF16(c, a, b) \
    asm volatile("mma.sync.aligned.m16n8k16.row.col.f32.bf16.bf16.f32 " \
        "{%0,%1,%2,%3}, {%4,%5,%6,%7}, {%8,%9}, {%0,%1,%2,%3};" \
        : "+f"((c)[0]), "+f"((c)[1]), "+f"((c)[2]), "+f"((c)[3]) \
        : "r"((a)[0]), "r"((a)[1]), "r"((a)[2]), "r"((a)[3]), \
          "r"((b)[0]), "r"((b)[1]))

#define LDMATRIX_X4(r0, r1, r2, r3, addr) \
    asm volatile("ldmatrix.sync.aligned.m8n8.x4.shared.b16 {%0,%1,%2,%3}, [%4];" \
        : "=r"(r0), "=r"(r1), "=r"(r2), "=r"(r3) : "r"(addr))

__device__ __forceinline__ void cp16(uint32_t dst, const void* src) {
    asm volatile("cp.async.ca.shared.global [%0], [%1], 16;" :: "r"(dst), "l"(src) : "memory");
}
#define CP_COMMIT() asm volatile("cp.async.commit_group;" ::: "memory")
#define CP_WAIT1()  asm volatile("cp.async.wait_group 1;" ::: "memory")
#define CP_WAIT0()  asm volatile("cp.async.wait_group 0;" ::: "memory")

// ---------------- kernel: zero Z ----------------
__global__ void zero_z_kernel() {
    int i = blockIdx.x * blockDim.x + threadIdx.x;
    if (i < TTOK) g_Z[i] = 0.0f;
}

// ---------------- kernel: build q (NCHW -> [T,C], L2 normalized, bf16) ----------------
__global__ void build_q_kernel(const float* __restrict__ x) {
    int bid = blockIdx.x;
    int n = bid >> 5, h = bid & 31;
    int tid = threadIdx.x;
    int w = tid & 31, cg = tid >> 5;

    __shared__ float ss[8][32];
    __shared__ float inv[32];
    __shared__ float xt[32][33];

    const float* xb = x + (size_t)n * (CDIM * HDIM * WDIM) + h * WDIM;

    float part = 0.0f;
    for (int c = cg; c < CDIM; c += 8) {
        float v = xb[c * 1024 + w];
        part += v * v;
    }
    ss[cg][w] = part;
    __syncthreads();
    if (tid < 32) {
        float s = 0.0f;
        #pragma unroll
        for (int g = 0; g < 8; g++) s += ss[g][tid];
        inv[tid] = 1.0f / fmaxf(sqrtf(s), EPSV);
    }
    __syncthreads();

    int t0 = n * 1024 + h * 32;
    int cl = tid & 31, tg = tid >> 5;
    for (int c0 = 0; c0 < CDIM; c0 += 32) {
        for (int ci = cg; ci < 32; ci += 8)
            xt[ci][w] = xb[(c0 + ci) * 1024 + w];
        __syncthreads();
        for (int tl = tg; tl < 32; tl += 8)
            g_qb[(size_t)(t0 + tl) * CDIM + c0 + cl] = __float2bfloat16(xt[cl][tl] * inv[tl]);
        __syncthreads();
    }
}

// ---------------- kernel: MLP GEMM  C = relu(A @ B^T + bias)  (SIMT fp32) ----------------
// 64(M) x 32(N) tile, BK=32, 256 threads, 4x2 micro-tile — more blocks, better occupancy
__global__ void mlp_gemm_kernel(const float* __restrict__ extA,
                                const float* __restrict__ Bw,
                                const float* __restrict__ bias,
                                int layer) {
    const float* A = layer ? (const float*)g_h : extA;
    float* Cc      = layer ? g_m : g_h;
    const int M = MEMN;
    const int N = layer ? CDIM : CHID;
    const int K = layer ? CHID : CDIM;

    int n0 = blockIdx.x * 32;
    int m0 = blockIdx.y * 64;

    __shared__ float As[32][68];
    __shared__ float Bs[32][36];

    int tid = threadIdx.x;
    int tx = tid & 15, ty = tid >> 4;
    float acc[4][2] = {};

    for (int k0 = 0; k0 < K; k0 += 32) {
        #pragma unroll
        for (int ii = 0; ii < 2; ii++) {
            int idx = tid + ii * 256;
            int r = idx >> 3, kq = (idx & 7) << 2;
            float4 v = make_float4(0.f, 0.f, 0.f, 0.f);
            if (m0 + r < M) v = *(const float4*)&A[(size_t)(m0 + r) * K + k0 + kq];
            As[kq + 0][r] = v.x; As[kq + 1][r] = v.y; As[kq + 2][r] = v.z; As[kq + 3][r] = v.w;
        }
        {
            int r = tid >> 3, kq = (tid & 7) << 2;
            float4 w = *(const float4*)&Bw[(size_t)(n0 + r) * K + k0 + kq];
            Bs[kq + 0][r] = w.x; Bs[kq + 1][r] = w.y; Bs[kq + 2][r] = w.z; Bs[kq + 3][r] = w.w;
        }
        __syncthreads();
        #pragma unroll
        for (int kk = 0; kk < 32; kk++) {
            float a[4], b[2];
            *(float4*)a = *(const float4*)&As[kk][tx * 4];
            *(float2*)b = *(const float2*)&Bs[kk][ty * 2];
            #pragma unroll
            for (int i = 0; i < 4; i++)
                #pragma unroll
                for (int j = 0; j < 2; j++)
                    acc[i][j] += a[i] * b[j];
        }
        __syncthreads();
    }

    #pragma unroll
    for (int j = 0; j < 2; j++) {
        int col = n0 + ty * 2 + j;
        float bv = bias[col];
        #pragma unroll
        for (int i = 0; i < 4; i++) {
            int row = m0 + tx * 4 + i;
            if (row < M) Cc[(size_t)row * N + col] = fmaxf(acc[i][j] + bv, 0.0f);
        }
    }
}

// ---------------- kernel: row L2-normalize m -> g_mnormb (bf16, zero pad) ----------------
__global__ void norm_rows_kernel() {
    int row = blockIdx.x;
    int tid = threadIdx.x;
    __nv_bfloat16* dst = &g_mnormb[(size_t)row * CDIM];
    if (row >= MEMN) {
        dst[tid] = __float2bfloat16(0.0f);
        dst[tid + 256] = __float2bfloat16(0.0f);
        return;
    }
    const float* src = &g_m[(size_t)row * CDIM];
    float v0 = src[tid], v1 = src[tid + 256];
    float ssv = v0 * v0 + v1 * v1;
    #pragma unroll
    for (int o = 16; o > 0; o >>= 1) ssv += __shfl_down_sync(0xffffffffu, ssv, o);
    __shared__ float red[8];
    __shared__ float sinv;
    if ((tid & 31) == 0) red[tid >> 5] = ssv;
    __syncthreads();
    if (tid == 0) {
        float s = 0.0f;
        #pragma unroll
        for (int i = 0; i < 8; i++) s += red[i];
        sinv = 1.0f / fmaxf(sqrtf(s), EPSV);
    }
    __syncthreads();
    dst[tid] = __float2bfloat16(v0 * sinv);
    dst[tid + 256] = __float2bfloat16(v1 * sinv);
}

// ---------------- kernel: transpose g_mnormb [J,C] -> g_mnormTb [C,J] ----------------
__global__ void transpose_m_kernel() {
    __shared__ __nv_bfloat16 t[32][34];
    int j0 = blockIdx.x * 32, c0 = blockIdx.y * 32;
    int lx = threadIdx.x, ly = threadIdx.y;   // 32 x 8
    #pragma unroll
    for (int ry = 0; ry < 32; ry += 8)
        t[ly + ry][lx] = g_mnormb[(size_t)(j0 + ly + ry) * CDIM + c0 + lx];
    __syncthreads();
    #pragma unroll
    for (int ry = 0; ry < 32; ry += 8)
        g_mnormTb[(size_t)(c0 + ly + ry) * MEMP + j0 + lx] = t[lx][ly + ry];
}

// ================ scores kernel: e = exp(q @ mnorm^T) -> att (fp32), Z sums ==================
// 128 tok x 128 mem tile, K=512, BK=64 elems (8 stages), cp.async double buffered
// fragment loads via ldmatrix.x4
__global__ __launch_bounds__(256, 2) void attn_scores_mma(float* __restrict__ att) {
    extern __shared__ float dsm[];
    float* bufA[2] = { dsm,        dsm + 4608 };
    float* bufB[2] = { dsm + 9216, dsm + 13824 };

    const int j0 = blockIdx.x * 128;
    const int t0 = blockIdx.y * 128;

    __shared__ float zsum[128];

    const int tid = threadIdx.x;
    const int lane = tid & 31, wid = tid >> 5;
    const int wm = wid & 1, wn = wid >> 1;
    const int g = lane >> 2, tg = lane & 3;

    if (tid < 128) zsum[tid] = 0.0f;

    uint32_t aA[2], aB[2];
    aA[0] = (uint32_t)__cvta_generic_to_shared(bufA[0]);
    aA[1] = (uint32_t)__cvta_generic_to_shared(bufA[1]);
    aB[0] = (uint32_t)__cvta_generic_to_shared(bufB[0]);
    aB[1] = (uint32_t)__cvta_generic_to_shared(bufB[1]);

    // per-lane ldmatrix base byte-offsets (within a buffer)
    uint32_t aoff[4], boff[2];
    {
        int lr = lane & 15, lc = lane >> 4;       // A: rows 0-15, col-chunk 0/1
        #pragma unroll
        for (int i = 0; i < 4; i++)
            aoff[i] = (uint32_t)(((wm * 64 + i * 16 + lr) * WSTRIDE64 + lc * 4) * 4);
        int q = lane >> 3, r8 = lane & 7;         // B: quad q -> (j-sub, k-chunk)
        #pragma unroll
        for (int jp = 0; jp < 2; jp++) {
            int jrow = wn * 32 + (jp * 2 + (q >> 1)) * 8 + r8;
            boff[jp] = (uint32_t)((jrow * WSTRIDE64 + (q & 1) * 4) * 4);
        }
    }

    const int r_ld = tid >> 3, q_ld = tid & 7;

    // prologue: stage 0
    #pragma unroll
    for (int i = 0; i < 4; i++) {
        int r = r_ld + i * 32;
        uint32_t doff = (uint32_t)(r * WSTRIDE64 + q_ld * 4) * 4;
        cp16(aA[0] + doff, &g_qb[(size_t)(t0 + r) * CDIM + q_ld * 8]);
        cp16(aB[0] + doff, &g_mnormb[(size_t)(j0 + r) * CDIM + q_ld * 8]);
    }
    CP_COMMIT();

    float acc[4][4][4] = {};

    #pragma unroll 1
    for (int it = 0; it < 8; ++it) {
        if (it + 1 < 8) {
            int nb = (it + 1) & 1;
            int k0 = (it + 1) * 64;
            #pragma unroll
            for (int i = 0; i < 4; i++) {
                int r = r_ld + i * 32;
                uint32_t doff = (uint32_t)(r * WSTRIDE64 + q_ld * 4) * 4;
                cp16(aA[nb] + doff, &g_qb[(size_t)(t0 + r) * CDIM + k0 + q_ld * 8]);
                cp16(aB[nb] + doff, &g_mnormb[(size_t)(j0 + r) * CDIM + k0 + q_ld * 8]);
            }
            CP_COMMIT();
            CP_WAIT1();
        } else {
            CP_WAIT0();
        }
        __syncthreads();

        const uint32_t Ab = aA[it & 1];
        const uint32_t Bb = aB[it & 1];
        #pragma unroll
        for (int kh = 0; kh < 4; kh++) {
            uint32_t kbyte = (uint32_t)(kh * 32);    // 8 words per k16 step
            uint32_t a[4][4], b[4][2];
            #pragma unroll
            for (int i = 0; i < 4; i++)
                LDMATRIX_X4(a[i][0], a[i][1], a[i][2], a[i][3], Ab + aoff[i] + kbyte);
            #pragma unroll
            for (int jp = 0; jp < 2; jp++)
                LDMATRIX_X4(b[jp * 2][0], b[jp * 2][1], b[jp * 2 + 1][0], b[jp * 2 + 1][1],
                            Bb + boff[jp] + kbyte);
            #pragma unroll
            for (int i = 0; i < 4; i++)
                #pragma unroll
                for (int j = 0; j < 4; j++)
                    MMA_BF16(acc[i][j], a[i], b[j]);
        }
        __syncthreads();
    }

    // epilogue: e = exp(score) -> att, Z reduction
    const int n = t0 >> 10, hwb = t0 & 1023;
    #pragma unroll
    for (int i = 0; i < 4; i++) {
        int r0 = wm * 64 + i * 16 + g;
        float z0 = 0.0f, z1 = 0.0f;
        #pragma unroll
        for (int j = 0; j < 4; j++) {
            int cb = wn * 32 + j * 8 + 2 * tg;
            #pragma unroll
            for (int cc = 0; cc < 2; cc++) {
                int jj = j0 + cb + cc;
                if (jj < MEMN) {
                    float e0 = __expf(acc[i][j][cc]);
                    float e1 = __expf(acc[i][j][cc + 2]);
                    size_t base = ((size_t)(n * MEMN + jj)) << 10;
                    att[base + hwb + r0] = e0;
                    att[base + hwb + r0 + 8] = e1;
                    z0 += e0; z1 += e1;
                }
            }
        }
        z0 += __shfl_xor_sync(0xffffffffu, z0, 1);
        z0 += __shfl_xor_sync(0xffffffffu, z0, 2);
        z1 += __shfl_xor_sync(0xffffffffu, z1, 1);
        z1 += __shfl_xor_sync(0xffffffffu, z1, 2);
        if (tg == 0) {
            atomicAdd(&zsum[r0], z0);
            atomicAdd(&zsum[r0 + 8], z1);
        }
    }
    __syncthreads();
    if (tid < 128) atomicAdd(&g_Z[t0 + tid], zsum[tid]);
}

// ================ l1 + activity flags kernel ==================
__global__ __launch_bounds__(256) void l1_flags_kernel(const float* __restrict__ att) {
    const int t0 = blockIdx.x * 128;
    const int n = t0 >> 10, hw0 = t0 & 1023;
    const int tid = threadIdx.x;
    const int tok = tid & 127, jh = tid >> 7;

    __shared__ float zinv_s[128];
    __shared__ float l1p[256];

    if (tid < 128) zinv_s[tid] = 1.0f / g_Z[t0 + tid];
    __syncthreads();

    const float ziv = zinv_s[tok];
    const float* ebase = att + (((size_t)n * MEMN) << 10) + hw0 + tok;

    float l1 = 0.0f;
    #pragma unroll 1
    for (int st = 0; st < 64; st++) {
        int jb = st * 32 + jh * 16;
        int flag = 0;
        #pragma unroll
        for (int i = 0; i < 16; i++) {
            int j = jb + i;
            float e = (j < MEMN) ? ebase[(size_t)j << 10] : 0.0f;
            float p = fmaxf(e * ziv - SHRINK, 0.0f);
            l1 += p;
            flag |= (p > 0.0f);
        }
        int act = __syncthreads_or(flag);
        if (tid == 0) g_flags[blockIdx.x * 64 + st] = act;
    }

    l1p[tid] = l1;
    __syncthreads();
    if (tid < 128) g_L1[t0 + tid] = l1p[tid] + l1p[tid + 128];
}

// ================ out kernel: out = (p @ mnorm)/L1, flag-gated stages ==================
__global__ __launch_bounds__(256, 2) void attn_out_mma(const float* __restrict__ att,
                                                       float* __restrict__ out) {
    extern __shared__ float dsm[];
    float* sA = dsm;                       // [128 tok][20 words] bf16 p-tile
    float* bufB[2] = { dsm + 2560, dsm + 5120 };

    const int c0b = blockIdx.x * 128;
    const int t0 = blockIdx.y * 128;
    const int n = t0 >> 10, hw0 = t0 & 1023;

    __shared__ float zinv_s[128];
    __shared__ float l1inv[128];
    __shared__ int sflags[64];

    const int tid = threadIdx.x;
    const int lane = tid & 31, wid = tid >> 5;
    const int wm = wid & 1, wn = wid >> 1;
    const int g = lane >> 2, tg = lane & 3;

    if (tid < 128) {
        zinv_s[tid] = 1.0f / g_Z[t0 + tid];
        l1inv[tid] = 1.0f / fmaxf(g_L1[t0 + tid], EPSV);
    }
    if (tid < 64) sflags[tid] = g_flags[blockIdx.y * 64 + tid];
    __syncthreads();

    const int tok = tid & 127, jh = tid >> 7;
    const float ziv = zinv_s[tok];
    const float* ebase = att + (((size_t)n * MEMN) << 10) + hw0 + tok;

    uint32_t aB[2];
    aB[0] = (uint32_t)__cvta_generic_to_shared(bufB[0]);
    aB[1] = (uint32_t)__cvta_generic_to_shared(bufB[1]);
    const int r_ld = tid >> 2, q_ld = tid & 3;

    float er[16];
    uint32_t* sAw = (uint32_t*)sA;

    // prologue: stage 0 (only if active)
    if (sflags[0]) {
        #pragma unroll
        for (int i = 0; i < 16; i++) {
            int j = jh * 16 + i;
            er[i] = (j < MEMN) ? ebase[(size_t)j << 10] : 0.0f;
        }
        #pragma unroll
        for (int i = 0; i < 2; i++) {
            int r = r_ld + i * 64;
            uint32_t doff = (uint32_t)(r * WSTRIDE + q_ld * 4) * 4;
            cp16(aB[0] + doff, &g_mnormTb[(size_t)(c0b + r) * MEMP + q_ld * 8]);
        }
    }
    CP_COMMIT();
    if (sflags[0]) {
        #pragma unroll
        for (int i = 0; i < 8; i++) {
            float p0 = fmaxf(er[2 * i] * ziv - SHRINK, 0.0f);
            float p1 = fmaxf(er[2 * i + 1] * ziv - SHRINK, 0.0f);
            __nv_bfloat162 pk = __floats2bfloat162_rn(p0, p1);
            sAw[tok * WSTRIDE + jh * 8 + i] = *(uint32_t*)&pk;
        }
    }

    float acc[4][4][4] = {};

    #pragma unroll 1
    for (int it = 0; it < 64; ++it) {
        int nxt_active = 0;
        if (it + 1 < 64) {
            nxt_active = sflags[it + 1];
            if (nxt_active) {
                int nb = (it + 1) & 1;
                int k0 = (it + 1) * 32;
                #pragma unroll
                for (int i = 0; i < 2; i++) {
                    int r = r_ld + i * 64;
                    uint32_t doff = (uint32_t)(r * WSTRIDE + q_ld * 4) * 4;
                    cp16(aB[nb] + doff, &g_mnormTb[(size_t)(c0b + r) * MEMP + k0 + q_ld * 8]);
                }
            }
            CP_COMMIT();   // empty group when inactive — keeps group counting consistent
            if (nxt_active) {
                int k0 = (it + 1) * 32;
                #pragma unroll
                for (int i = 0; i < 16; i++) {
                    int j = k0 + jh * 16 + i;
                    er[i] = (j < MEMN) ? ebase[(size_t)j << 10] : 0.0f;
                }
            }
            CP_WAIT1();
        } else {
            CP_WAIT0();
        }
        __syncthreads();   // sA stores + B(it) visible

        if (sflags[it]) {
            const uint32_t* Bs = (const uint32_t*)bufB[it & 1];
            #pragma unroll
            for (int kh = 0; kh < 2; kh++) {
                int ko = kh * 8;
                uint32_t a[4][4], b[4][2];
                #pragma unroll
                for (int i = 0; i < 4; i++) {
                    const uint32_t* ap = &sAw[(wm * 64 + i * 16 + g) * WSTRIDE + ko + tg];
                    a[i][0] = ap[0];
                    a[i][1] = ap[8 * WSTRIDE];
                    a[i][2] = ap[4];
                    a[i][3] = ap[8 * WSTRIDE + 4];
                }
                #pragma unroll
                for (int j = 0; j < 4; j++) {
                    const uint32_t* bp = &Bs[(wn * 32 + j * 8 + g) * WSTRIDE + ko + tg];
                    b[j][0] = bp[0];
                    b[j][1] = bp[4];
                }
                #pragma unroll
                for (int i = 0; i < 4; i++)
                    #pragma unroll
                    for (int j = 0; j < 4; j++)
                        MMA_BF16(acc[i][j], a[i], b[j]);
            }
        }
        __syncthreads();   // MMA reads of sA done before overwrite

        if (nxt_active) {
            #pragma unroll
            for (int i = 0; i < 8; i++) {
                float p0 = fmaxf(er[2 * i] * ziv - SHRINK, 0.0f);
                float p1 = fmaxf(er[2 * i + 1] * ziv - SHRINK, 0.0f);
                __nv_bfloat162 pk = __floats2bfloat162_rn(p0, p1);
                sAw[tok * WSTRIDE + jh * 8 + i] = *(uint32_t*)&pk;
            }
        }
    }

    // epilogue: write out NCHW scaled by 1/L1
    #pragma unroll
    for (int i = 0; i < 4; i++) {
        int r0 = wm * 64 + i * 16 + g;
        float li0 = l1inv[r0], li1 = l1inv[r0 + 8];
        #pragma unroll
        for (int j = 0; j < 4; j++) {
            int cb = c0b + wn * 32 + j * 8 + 2 * tg;
            #pragma unroll
            for (int cc = 0; cc < 2; cc++) {
                size_t base = ((size_t)(n * CDIM + cb + cc)) << 10;
                out[base + hw0 + r0]     = acc[i][j][cc]     * li0;
                out[base + hw0 + r0 + 8] = acc[i][j][cc + 2] * li1;
            }
        }
    }
}

// ---------------- finalize att_r = relu(e/Z - SHRINK)/max(L1,eps), flag-gated ----------------
// inactive (token-tile, stage) blocks are exactly zero -> write zeros, skip the e read
__global__ void att_finalize_kernel(float* __restrict__ att) {
    int b = blockIdx.x;           // n*MEMN + j
    int n = b / MEMN;
    int j = b - n * MEMN;
    int tid = threadIdx.x;
    size_t base = ((size_t)b << 10) + (tid << 2);
    int hw = tid << 2;

    int tile = n * 8 + (hw >> 7);            // 128-token tile index
    int flag = g_flags[tile * 64 + (j >> 5)];
    if (!flag) {
        *(float4*)&att[base] = make_float4(0.0f, 0.0f, 0.0f, 0.0f);
        return;
    }

    int t = (n << 10) + hw;
    float4 e = *(float4*)&att[base];
    float4 z = *(const float4*)&g_Z[t];
    float4 l = *(const float4*)&g_L1[t];

    float4 r;
    r.x = fmaxf(e.x * (1.0f / z.x) - SHRINK, 0.0f) * (1.0f / fmaxf(l.x, EPSV));
    r.y = fmaxf(e.y * (1.0f / z.y) - SHRINK, 0.0f) * (1.0f / fmaxf(l.y, EPSV));
    r.z = fmaxf(e.z * (1.0f / z.z) - SHRINK, 0.0f) * (1.0f / fmaxf(l.z, EPSV));
    r.w = fmaxf(e.w * (1.0f / z.w) - SHRINK, 0.0f) * (1.0f / fmaxf(l.w, EPSV));
    *(float4*)&att[base] = r;
}

// ---------------- launch ----------------
extern "C" void kernel_launch(void* const* d_in, const int* in_sizes, int n_in,
                              void* d_out, int out_size) {
    const float* x      = (const float*)d_in[0];
    const float* memory = (const float*)d_in[1];
    const float* w1     = (const float*)d_in[2];
    const float* b1     = (const float*)d_in[3];
    const float* w2     = (const float*)d_in[4];
    const float* b2     = (const float*)d_in[5];

    float* out = (float*)d_out;
    float* att = out + OUT_ELEMS;

    cudaFuncSetAttribute(attn_scores_mma, cudaFuncAttributeMaxDynamicSharedMemorySize, 73728);

    zero_z_kernel<<<TTOK / 256, 256>>>();
    build_q_kernel<<<NIMG * HDIM, 256>>>(x);
    mlp_gemm_kernel<<<dim3(CHID / 32, (MEMN + 63) / 64), 256>>>(memory, w1, b1, 0);
    mlp_gemm_kernel<<<dim3(CDIM / 32, (MEMN + 63) / 64), 256>>>(nullptr, w2, b2, 1);
    norm_rows_kernel<<<MEMP, 256>>>();
    transpose_m_kernel<<<dim3(MEMP / 32, CDIM / 32), dim3(32, 8)>>>();
    attn_scores_mma<<<dim3(MEMP / 128, TTOK / 128), 256, 73728>>>(att);
    l1_flags_kernel<<<TTOK / 128, 256>>>(att);
    attn_out_mma<<<dim3(CDIM / 128, TTOK / 128), 256, 30720>>>(att, out);
    att_finalize_kernel<<<NIMG * MEMN, 256>>>(att);
}

// round 15
// speedup vs baseline: 1.3657x; 1.0242x over previous
#include <cuda_runtime.h>
#include <cuda_bf16.h>
#include <cstdint>
#include <math.h>

// ---------------- problem constants ----------------
#define NIMG 16
#define CDIM 512
#define HDIM 32
#define WDIM 32
#define TTOK (NIMG*HDIM*WDIM)      // 16384
#define MEMN 2000
#define MEMP 2048                   // padded
#define CHID 256
#define SHRINK 0.0025f
#define EPSV 1e-12f

#define OUT_ELEMS ((size_t)NIMG*CDIM*HDIM*WDIM)   // 8388608

// row strides (bf16 halfs / 32-bit words), conflict-free fragment loads
#define HSTRIDE 40
#define WSTRIDE 20
#define HSTRIDE64 72
#define WSTRIDE64 36

// ---------------- scratch (device globals) ----------------
__device__ __nv_bfloat16 g_qb[(size_t)TTOK * CDIM];       // bf16 queries [T,C]
__device__ float g_h[(size_t)MEMN * CHID];                 // MLP hidden (fp32)
__device__ float g_m[(size_t)MEMN * CDIM];                 // MLP out (pre-norm, fp32)
__device__ __nv_bfloat16 g_mnormb[(size_t)MEMP * CDIM];   // normalized memory [J,C] bf16, zero pad
__device__ __nv_bfloat16 g_mnormTb[(size_t)CDIM * MEMP];  // transposed [C,J] bf16, zero pad
__device__ float g_Z[TTOK];
__device__ float g_L1[TTOK];
__device__ int   g_flags[(TTOK / 128) * 64];               // per (token-tile, 32-mem stage) activity

#define MMA_BF16(c, a, b) \
    asm volatile("mma.sync.aligned.m16n8k16.row.col.f32.bf16.bf16.f32 " \
        "{%0,%1,%2,%3}, {%4,%5,%6,%7}, {%8,%9}, {%0,%1,%2,%3};" \
        : "+f"((c)[0]), "+f"((c)[1]), "+f"((c)[2]), "+f"((c)[3]) \
        : "r"((a)[0]), "r"((a)[1]), "r"((a)[2]), "r"((a)[3]), \
          "r"((b)[0]), "r"((b)[1]))

#define LDMATRIX_X4(r0, r1, r2, r3, addr) \
    asm volatile("ldmatrix.sync.aligned.m8n8.x4.shared.b16 {%0,%1,%2,%3}, [%4];" \
        : "=r"(r0), "=r"(r1), "=r"(r2), "=r"(r3) : "r"(addr))

__device__ __forceinline__ void cp16(uint32_t dst, const void* src) {
    asm volatile("cp.async.ca.shared.global [%0], [%1], 16;" :: "r"(dst), "l"(src) : "memory");
}
#define CP_COMMIT() asm volatile("cp.async.commit_group;" ::: "memory")
#define CP_WAIT1()  asm volatile("cp.async.wait_group 1;" ::: "memory")
#define CP_WAIT0()  asm volatile("cp.async.wait_group 0;" ::: "memory")

// ---------------- kernel: zero Z ----------------
__global__ void zero_z_kernel() {
    int i = blockIdx.x * blockDim.x + threadIdx.x;
    if (i < TTOK) g_Z[i] = 0.0f;
}

// ---------------- kernel: build q (NCHW -> [T,C], L2 normalized, bf16) ----------------
__global__ void build_q_kernel(const float* __restrict__ x) {
    int bid = blockIdx.x;
    int n = bid >> 5, h = bid & 31;
    int tid = threadIdx.x;
    int w = tid & 31, cg = tid >> 5;

    __shared__ float ss[8][32];
    __shared__ float inv[32];
    __shared__ float xt[32][33];

    const float* xb = x + (size_t)n * (CDIM * HDIM * WDIM) + h * WDIM;

    float part = 0.0f;
    for (int c = cg; c < CDIM; c += 8) {
        float v = xb[c * 1024 + w];
        part += v * v;
    }
    ss[cg][w] = part;
    __syncthreads();
    if (tid < 32) {
        float s = 0.0f;
        #pragma unroll
        for (int g = 0; g < 8; g++) s += ss[g][tid];
        inv[tid] = 1.0f / fmaxf(sqrtf(s), EPSV);
    }
    __syncthreads();

    int t0 = n * 1024 + h * 32;
    int cl = tid & 31, tg = tid >> 5;
    for (int c0 = 0; c0 < CDIM; c0 += 32) {
        for (int ci = cg; ci < 32; ci += 8)
            xt[ci][w] = xb[(c0 + ci) * 1024 + w];
        __syncthreads();
        for (int tl = tg; tl < 32; tl += 8)
            g_qb[(size_t)(t0 + tl) * CDIM + c0 + cl] = __float2bfloat16(xt[cl][tl] * inv[tl]);
        __syncthreads();
    }
}

// ---------------- kernel: MLP GEMM  C = relu(A @ B^T + bias)  (SIMT fp32, 64x64, R10-proven) ----------------
__global__ void mlp_gemm_kernel(const float* __restrict__ extA,
                                const float* __restrict__ Bw,
                                const float* __restrict__ bias,
                                int layer) {
    const float* A = layer ? (const float*)g_h : extA;
    float* Cc      = layer ? g_m : g_h;
    const int M = MEMN;
    const int N = layer ? CDIM : CHID;
    const int K = layer ? CHID : CDIM;

    int n0 = blockIdx.x * 64;
    int m0 = blockIdx.y * 64;

    __shared__ float As[32][68];
    __shared__ float Bs[32][68];

    int tid = threadIdx.x;
    int tx = tid & 15, ty = tid >> 4;
    float acc[4][4] = {};

    for (int k0 = 0; k0 < K; k0 += 32) {
        for (int idx = tid; idx < 512; idx += 256) {
            int r = idx >> 3, kq = (idx & 7) << 2;
            float4 v = make_float4(0.f, 0.f, 0.f, 0.f);
            if (m0 + r < M) v = *(const float4*)&A[(size_t)(m0 + r) * K + k0 + kq];
            As[kq + 0][r] = v.x; As[kq + 1][r] = v.y; As[kq + 2][r] = v.z; As[kq + 3][r] = v.w;
            float4 w = *(const float4*)&Bw[(size_t)(n0 + r) * K + k0 + kq];
            Bs[kq + 0][r] = w.x; Bs[kq + 1][r] = w.y; Bs[kq + 2][r] = w.z; Bs[kq + 3][r] = w.w;
        }
        __syncthreads();
        #pragma unroll
        for (int kk = 0; kk < 32; kk++) {
            float a[4], b[4];
            *(float4*)a = *(const float4*)&As[kk][tx * 4];
            *(float4*)b = *(const float4*)&Bs[kk][ty * 4];
            #pragma unroll
            for (int i = 0; i < 4; i++)
                #pragma unroll
                for (int j = 0; j < 4; j++)
                    acc[i][j] += a[i] * b[j];
        }
        __syncthreads();
    }

    #pragma unroll
    for (int j = 0; j < 4; j++) {
        int col = n0 + ty * 4 + j;
        float bv = bias[col];
        #pragma unroll
        for (int i = 0; i < 4; i++) {
            int row = m0 + tx * 4 + i;
            if (row < M) Cc[(size_t)row * N + col] = fmaxf(acc[i][j] + bv, 0.0f);
        }
    }
}

// ---------------- kernel: row L2-normalize m -> g_mnormb (bf16, zero pad) ----------------
__global__ void norm_rows_kernel() {
    int row = blockIdx.x;
    int tid = threadIdx.x;
    __nv_bfloat16* dst = &g_mnormb[(size_t)row * CDIM];
    if (row >= MEMN) {
        dst[tid] = __float2bfloat16(0.0f);
        dst[tid + 256] = __float2bfloat16(0.0f);
        return;
    }
    const float* src = &g_m[(size_t)row * CDIM];
    float v0 = src[tid], v1 = src[tid + 256];
    float ssv = v0 * v0 + v1 * v1;
    #pragma unroll
    for (int o = 16; o > 0; o >>= 1) ssv += __shfl_down_sync(0xffffffffu, ssv, o);
    __shared__ float red[8];
    __shared__ float sinv;
    if ((tid & 31) == 0) red[tid >> 5] = ssv;
    __syncthreads();
    if (tid == 0) {
        float s = 0.0f;
        #pragma unroll
        for (int i = 0; i < 8; i++) s += red[i];
        sinv = 1.0f / fmaxf(sqrtf(s), EPSV);
    }
    __syncthreads();
    dst[tid] = __float2bfloat16(v0 * sinv);
    dst[tid + 256] = __float2bfloat16(v1 * sinv);
}

// ---------------- kernel: transpose g_mnormb [J,C] -> g_mnormTb [C,J] ----------------
__global__ void transpose_m_kernel() {
    __shared__ __nv_bfloat16 t[32][34];
    int j0 = blockIdx.x * 32, c0 = blockIdx.y * 32;
    int lx = threadIdx.x, ly = threadIdx.y;   // 32 x 8
    #pragma unroll
    for (int ry = 0; ry < 32; ry += 8)
        t[ly + ry][lx] = g_mnormb[(size_t)(j0 + ly + ry) * CDIM + c0 + lx];
    __syncthreads();
    #pragma unroll
    for (int ry = 0; ry < 32; ry += 8)
        g_mnormTb[(size_t)(c0 + ly + ry) * MEMP + j0 + lx] = t[lx][ly + ry];
}

// ================ scores kernel: e = exp(q @ mnorm^T) -> att (fp32), Z sums ==================
// 128 tok x 128 mem tile, K=512, BK=64 elems (8 stages), cp.async double buffered
// fragment loads via ldmatrix.x4
__global__ __launch_bounds__(256, 2) void attn_scores_mma(float* __restrict__ att) {
    extern __shared__ float dsm[];
    float* bufA[2] = { dsm,        dsm + 4608 };
    float* bufB[2] = { dsm + 9216, dsm + 13824 };

    const int j0 = blockIdx.x * 128;
    const int t0 = blockIdx.y * 128;

    __shared__ float zsum[128];

    const int tid = threadIdx.x;
    const int lane = tid & 31, wid = tid >> 5;
    const int wm = wid & 1, wn = wid >> 1;
    const int g = lane >> 2, tg = lane & 3;

    if (tid < 128) zsum[tid] = 0.0f;

    uint32_t aA[2], aB[2];
    aA[0] = (uint32_t)__cvta_generic_to_shared(bufA[0]);
    aA[1] = (uint32_t)__cvta_generic_to_shared(bufA[1]);
    aB[0] = (uint32_t)__cvta_generic_to_shared(bufB[0]);
    aB[1] = (uint32_t)__cvta_generic_to_shared(bufB[1]);

    // per-lane ldmatrix base byte-offsets (within a buffer)
    uint32_t aoff[4], boff[2];
    {
        int lr = lane & 15, lc = lane >> 4;       // A: rows 0-15, col-chunk 0/1
        #pragma unroll
        for (int i = 0; i < 4; i++)
            aoff[i] = (uint32_t)(((wm * 64 + i * 16 + lr) * WSTRIDE64 + lc * 4) * 4);
        int q = lane >> 3, r8 = lane & 7;         // B: quad q -> (j-sub, k-chunk)
        #pragma unroll
        for (int jp = 0; jp < 2; jp++) {
            int jrow = wn * 32 + (jp * 2 + (q >> 1)) * 8 + r8;
            boff[jp] = (uint32_t)((jrow * WSTRIDE64 + (q & 1) * 4) * 4);
        }
    }

    const int r_ld = tid >> 3, q_ld = tid & 7;

    // prologue: stage 0
    #pragma unroll
    for (int i = 0; i < 4; i++) {
        int r = r_ld + i * 32;
        uint32_t doff = (uint32_t)(r * WSTRIDE64 + q_ld * 4) * 4;
        cp16(aA[0] + doff, &g_qb[(size_t)(t0 + r) * CDIM + q_ld * 8]);
        cp16(aB[0] + doff, &g_mnormb[(size_t)(j0 + r) * CDIM + q_ld * 8]);
    }
    CP_COMMIT();

    float acc[4][4][4] = {};

    #pragma unroll 1
    for (int it = 0; it < 8; ++it) {
        if (it + 1 < 8) {
            int nb = (it + 1) & 1;
            int k0 = (it + 1) * 64;
            #pragma unroll
            for (int i = 0; i < 4; i++) {
                int r = r_ld + i * 32;
                uint32_t doff = (uint32_t)(r * WSTRIDE64 + q_ld * 4) * 4;
                cp16(aA[nb] + doff, &g_qb[(size_t)(t0 + r) * CDIM + k0 + q_ld * 8]);
                cp16(aB[nb] + doff, &g_mnormb[(size_t)(j0 + r) * CDIM + k0 + q_ld * 8]);
            }
            CP_COMMIT();
            CP_WAIT1();
        } else {
            CP_WAIT0();
        }
        __syncthreads();

        const uint32_t Ab = aA[it & 1];
        const uint32_t Bb = aB[it & 1];
        #pragma unroll
        for (int kh = 0; kh < 4; kh++) {
            uint32_t kbyte = (uint32_t)(kh * 32);    // 8 words per k16 step
            uint32_t a[4][4], b[4][2];
            #pragma unroll
            for (int i = 0; i < 4; i++)
                LDMATRIX_X4(a[i][0], a[i][1], a[i][2], a[i][3], Ab + aoff[i] + kbyte);
            #pragma unroll
            for (int jp = 0; jp < 2; jp++)
                LDMATRIX_X4(b[jp * 2][0], b[jp * 2][1], b[jp * 2 + 1][0], b[jp * 2 + 1][1],
                            Bb + boff[jp] + kbyte);
            #pragma unroll
            for (int i = 0; i < 4; i++)
                #pragma unroll
                for (int j = 0; j < 4; j++)
                    MMA_BF16(acc[i][j], a[i], b[j]);
        }
        __syncthreads();
    }

    // epilogue: e = exp(score) -> att, Z reduction
    const int n = t0 >> 10, hwb = t0 & 1023;
    #pragma unroll
    for (int i = 0; i < 4; i++) {
        int r0 = wm * 64 + i * 16 + g;
        float z0 = 0.0f, z1 = 0.0f;
        #pragma unroll
        for (int j = 0; j < 4; j++) {
            int cb = wn * 32 + j * 8 + 2 * tg;
            #pragma unroll
            for (int cc = 0; cc < 2; cc++) {
                int jj = j0 + cb + cc;
                if (jj < MEMN) {
                    float e0 = __expf(acc[i][j][cc]);
                    float e1 = __expf(acc[i][j][cc + 2]);
                    size_t base = ((size_t)(n * MEMN + jj)) << 10;
                    att[base + hwb + r0] = e0;
                    att[base + hwb + r0 + 8] = e1;
                    z0 += e0; z1 += e1;
                }
            }
        }
        z0 += __shfl_xor_sync(0xffffffffu, z0, 1);
        z0 += __shfl_xor_sync(0xffffffffu, z0, 2);
        z1 += __shfl_xor_sync(0xffffffffu, z1, 1);
        z1 += __shfl_xor_sync(0xffffffffu, z1, 2);
        if (tg == 0) {
            atomicAdd(&zsum[r0], z0);
            atomicAdd(&zsum[r0 + 8], z1);
        }
    }
    __syncthreads();
    if (tid < 128) atomicAdd(&g_Z[t0 + tid], zsum[tid]);
}

// ================ l1 + activity flags kernel ==================
__global__ __launch_bounds__(256) void l1_flags_kernel(const float* __restrict__ att) {
    const int t0 = blockIdx.x * 128;
    const int n = t0 >> 10, hw0 = t0 & 1023;
    const int tid = threadIdx.x;
    const int tok = tid & 127, jh = tid >> 7;

    __shared__ float zinv_s[128];
    __shared__ float l1p[256];

    if (tid < 128) zinv_s[tid] = 1.0f / g_Z[t0 + tid];
    __syncthreads();

    const float ziv = zinv_s[tok];
    const float* ebase = att + (((size_t)n * MEMN) << 10) + hw0 + tok;

    float l1 = 0.0f;
    #pragma unroll 1
    for (int st = 0; st < 64; st++) {
        int jb = st * 32 + jh * 16;
        int flag = 0;
        #pragma unroll
        for (int i = 0; i < 16; i++) {
            int j = jb + i;
            float e = (j < MEMN) ? ebase[(size_t)j << 10] : 0.0f;
            float p = fmaxf(e * ziv - SHRINK, 0.0f);
            l1 += p;
            flag |= (p > 0.0f);
        }
        int act = __syncthreads_or(flag);
        if (tid == 0) g_flags[blockIdx.x * 64 + st] = act;
    }

    l1p[tid] = l1;
    __syncthreads();
    if (tid < 128) g_L1[t0 + tid] = l1p[tid] + l1p[tid + 128];
}

// ================ out kernel: out = (p @ mnorm)/L1, flag-gated stages ==================
__global__ __launch_bounds__(256, 2) void attn_out_mma(const float* __restrict__ att,
                                                       float* __restrict__ out) {
    extern __shared__ float dsm[];
    float* sA = dsm;                       // [128 tok][20 words] bf16 p-tile
    float* bufB[2] = { dsm + 2560, dsm + 5120 };

    const int c0b = blockIdx.x * 128;
    const int t0 = blockIdx.y * 128;
    const int n = t0 >> 10, hw0 = t0 & 1023;

    __shared__ float zinv_s[128];
    __shared__ float l1inv[128];
    __shared__ int sflags[64];

    const int tid = threadIdx.x;
    const int lane = tid & 31, wid = tid >> 5;
    const int wm = wid & 1, wn = wid >> 1;
    const int g = lane >> 2, tg = lane & 3;

    if (tid < 128) {
        zinv_s[tid] = 1.0f / g_Z[t0 + tid];
        l1inv[tid] = 1.0f / fmaxf(g_L1[t0 + tid], EPSV);
    }
    if (tid < 64) sflags[tid] = g_flags[blockIdx.y * 64 + tid];
    __syncthreads();

    const int tok = tid & 127, jh = tid >> 7;
    const float ziv = zinv_s[tok];
    const float* ebase = att + (((size_t)n * MEMN) << 10) + hw0 + tok;

    uint32_t aB[2];
    aB[0] = (uint32_t)__cvta_generic_to_shared(bufB[0]);
    aB[1] = (uint32_t)__cvta_generic_to_shared(bufB[1]);
    const int r_ld = tid >> 2, q_ld = tid & 3;

    float er[16];
    uint32_t* sAw = (uint32_t*)sA;

    // prologue: stage 0 (only if active)
    if (sflags[0]) {
        #pragma unroll
        for (int i = 0; i < 16; i++) {
            int j = jh * 16 + i;
            er[i] = (j < MEMN) ? ebase[(size_t)j << 10] : 0.0f;
        }
        #pragma unroll
        for (int i = 0; i < 2; i++) {
            int r = r_ld + i * 64;
            uint32_t doff = (uint32_t)(r * WSTRIDE + q_ld * 4) * 4;
            cp16(aB[0] + doff, &g_mnormTb[(size_t)(c0b + r) * MEMP + q_ld * 8]);
        }
    }
    CP_COMMIT();
    if (sflags[0]) {
        #pragma unroll
        for (int i = 0; i < 8; i++) {
            float p0 = fmaxf(er[2 * i] * ziv - SHRINK, 0.0f);
            float p1 = fmaxf(er[2 * i + 1] * ziv - SHRINK, 0.0f);
            __nv_bfloat162 pk = __floats2bfloat162_rn(p0, p1);
            sAw[tok * WSTRIDE + jh * 8 + i] = *(uint32_t*)&pk;
        }
    }

    float acc[4][4][4] = {};

    #pragma unroll 1
    for (int it = 0; it < 64; ++it) {
        int nxt_active = 0;
        if (it + 1 < 64) {
            nxt_active = sflags[it + 1];
            if (nxt_active) {
                int nb = (it + 1) & 1;
                int k0 = (it + 1) * 32;
                #pragma unroll
                for (int i = 0; i < 2; i++) {
                    int r = r_ld + i * 64;
                    uint32_t doff = (uint32_t)(r * WSTRIDE + q_ld * 4) * 4;
                    cp16(aB[nb] + doff, &g_mnormTb[(size_t)(c0b + r) * MEMP + k0 + q_ld * 8]);
                }
            }
            CP_COMMIT();   // empty group when inactive — keeps group counting consistent
            if (nxt_active) {
                int k0 = (it + 1) * 32;
                #pragma unroll
                for (int i = 0; i < 16; i++) {
                    int j = k0 + jh * 16 + i;
                    er[i] = (j < MEMN) ? ebase[(size_t)j << 10] : 0.0f;
                }
            }
            CP_WAIT1();
        } else {
            CP_WAIT0();
        }
        __syncthreads();   // sA stores + B(it) visible

        if (sflags[it]) {
            const uint32_t* Bs = (const uint32_t*)bufB[it & 1];
            #pragma unroll
            for (int kh = 0; kh < 2; kh++) {
                int ko = kh * 8;
                uint32_t a[4][4], b[4][2];
                #pragma unroll
                for (int i = 0; i < 4; i++) {
                    const uint32_t* ap = &sAw[(wm * 64 + i * 16 + g) * WSTRIDE + ko + tg];
                    a[i][0] = ap[0];
                    a[i][1] = ap[8 * WSTRIDE];
                    a[i][2] = ap[4];
                    a[i][3] = ap[8 * WSTRIDE + 4];
                }
                #pragma unroll
                for (int j = 0; j < 4; j++) {
                    const uint32_t* bp = &Bs[(wn * 32 + j * 8 + g) * WSTRIDE + ko + tg];
                    b[j][0] = bp[0];
                    b[j][1] = bp[4];
                }
                #pragma unroll
                for (int i = 0; i < 4; i++)
                    #pragma unroll
                    for (int j = 0; j < 4; j++)
                        MMA_BF16(acc[i][j], a[i], b[j]);
            }
        }
        __syncthreads();   // MMA reads of sA done before overwrite

        if (nxt_active) {
            #pragma unroll
            for (int i = 0; i < 8; i++) {
                float p0 = fmaxf(er[2 * i] * ziv - SHRINK, 0.0f);
                float p1 = fmaxf(er[2 * i + 1] * ziv - SHRINK, 0.0f);
                __nv_bfloat162 pk = __floats2bfloat162_rn(p0, p1);
                sAw[tok * WSTRIDE + jh * 8 + i] = *(uint32_t*)&pk;
            }
        }
    }

    // epilogue: write out NCHW scaled by 1/L1
    #pragma unroll
    for (int i = 0; i < 4; i++) {
        int r0 = wm * 64 + i * 16 + g;
        float li0 = l1inv[r0], li1 = l1inv[r0 + 8];
        #pragma unroll
        for (int j = 0; j < 4; j++) {
            int cb = c0b + wn * 32 + j * 8 + 2 * tg;
            #pragma unroll
            for (int cc = 0; cc < 2; cc++) {
                size_t base = ((size_t)(n * CDIM + cb + cc)) << 10;
                out[base + hw0 + r0]     = acc[i][j][cc]     * li0;
                out[base + hw0 + r0 + 8] = acc[i][j][cc + 2] * li1;
            }
        }
    }
}

// ---------------- finalize att_r = relu(e/Z - SHRINK)/max(L1,eps), flag-gated ----------------
__global__ void att_finalize_kernel(float* __restrict__ att) {
    int b = blockIdx.x;           // n*MEMN + j
    int n = b / MEMN;
    int j = b - n * MEMN;
    int tid = threadIdx.x;
    size_t base = ((size_t)b << 10) + (tid << 2);
    int hw = tid << 2;

    int tile = n * 8 + (hw >> 7);            // 128-token tile index
    int flag = g_flags[tile * 64 + (j >> 5)];
    if (!flag) {
        *(float4*)&att[base] = make_float4(0.0f, 0.0f, 0.0f, 0.0f);
        return;
    }

    int t = (n << 10) + hw;
    float4 e = *(float4*)&att[base];
    float4 z = *(const float4*)&g_Z[t];
    float4 l = *(const float4*)&g_L1[t];

    float4 r;
    r.x = fmaxf(e.x * (1.0f / z.x) - SHRINK, 0.0f) * (1.0f / fmaxf(l.x, EPSV));
    r.y = fmaxf(e.y * (1.0f / z.y) - SHRINK, 0.0f) * (1.0f / fmaxf(l.y, EPSV));
    r.z = fmaxf(e.z * (1.0f / z.z) - SHRINK, 0.0f) * (1.0f / fmaxf(l.z, EPSV));
    r.w = fmaxf(e.w * (1.0f / z.w) - SHRINK, 0.0f) * (1.0f / fmaxf(l.w, EPSV));
    *(float4*)&att[base] = r;
}

// ---------------- launch ----------------
extern "C" void kernel_launch(void* const* d_in, const int* in_sizes, int n_in,
                              void* d_out, int out_size) {
    const float* x      = (const float*)d_in[0];
    const float* memory = (const float*)d_in[1];
    const float* w1     = (const float*)d_in[2];
    const float* b1     = (const float*)d_in[3];
    const float* w2     = (const float*)d_in[4];
    const float* b2     = (const float*)d_in[5];

    float* out = (float*)d_out;
    float* att = out + OUT_ELEMS;

    cudaFuncSetAttribute(attn_scores_mma, cudaFuncAttributeMaxDynamicSharedMemorySize, 73728);

    zero_z_kernel<<<TTOK / 256, 256>>>();
    build_q_kernel<<<NIMG * HDIM, 256>>>(x);
    mlp_gemm_kernel<<<dim3(CHID / 64, (MEMN + 63) / 64), 256>>>(memory, w1, b1, 0);
    mlp_gemm_kernel<<<dim3(CDIM / 64, (MEMN + 63) / 64), 256>>>(nullptr, w2, b2, 1);
    norm_rows_kernel<<<MEMP, 256>>>();
    transpose_m_kernel<<<dim3(MEMP / 32, CDIM / 32), dim3(32, 8)>>>();
    attn_scores_mma<<<dim3(MEMP / 128, TTOK / 128), 256, 73728>>>(att);
    l1_flags_kernel<<<TTOK / 128, 256>>>(att);
    attn_out_mma<<<dim3(CDIM / 128, TTOK / 128), 256, 30720>>>(att, out);
    att_finalize_kernel<<<NIMG * MEMN, 256>>>(att);
}

// round 16
// speedup vs baseline: 1.4285x; 1.0460x over previous
#include <cuda_runtime.h>
#include <cuda_bf16.h>
#include <cstdint>
#include <math.h>

// ---------------- problem constants ----------------
#define NIMG 16
#define CDIM 512
#define HDIM 32
#define WDIM 32
#define TTOK (NIMG*HDIM*WDIM)      // 16384
#define MEMN 2000
#define MEMP 2048                   // padded
#define CHID 256
#define SHRINK 0.0025f
#define EPSV 1e-12f

#define OUT_ELEMS ((size_t)NIMG*CDIM*HDIM*WDIM)   // 8388608

// row strides (bf16 halfs / 32-bit words), conflict-free fragment loads
#define HSTRIDE 40
#define WSTRIDE 20
#define HSTRIDE64 72
#define WSTRIDE64 36

// ---------------- scratch (device globals) ----------------
__device__ __nv_bfloat16 g_qb[(size_t)TTOK * CDIM];       // bf16 queries [T,C]
__device__ float g_h[(size_t)MEMN * CHID];                 // MLP hidden (fp32)
__device__ float g_m[(size_t)MEMN * CDIM];                 // MLP out (pre-norm, fp32)
__device__ __nv_bfloat16 g_mnormb[(size_t)MEMP * CDIM];   // normalized memory [J,C] bf16, zero pad
__device__ __nv_bfloat16 g_mnormTb[(size_t)CDIM * MEMP];  // transposed [C,J] bf16, zero pad
__device__ float g_Z[TTOK];
__device__ int   g_flags[(TTOK / 128) * 64];               // per (token-tile, 32-mem stage) activity

#define MMA_BF16(c, a, b) \
    asm volatile("mma.sync.aligned.m16n8k16.row.col.f32.bf16.bf16.f32 " \
        "{%0,%1,%2,%3}, {%4,%5,%6,%7}, {%8,%9}, {%0,%1,%2,%3};" \
        : "+f"((c)[0]), "+f"((c)[1]), "+f"((c)[2]), "+f"((c)[3]) \
        : "r"((a)[0]), "r"((a)[1]), "r"((a)[2]), "r"((a)[3]), \
          "r"((b)[0]), "r"((b)[1]))

#define LDMATRIX_X4(r0, r1, r2, r3, addr) \
    asm volatile("ldmatrix.sync.aligned.m8n8.x4.shared.b16 {%0,%1,%2,%3}, [%4];" \
        : "=r"(r0), "=r"(r1), "=r"(r2), "=r"(r3) : "r"(addr))

__device__ __forceinline__ void cp16(uint32_t dst, const void* src) {
    asm volatile("cp.async.ca.shared.global [%0], [%1], 16;" :: "r"(dst), "l"(src) : "memory");
}
#define CP_COMMIT() asm volatile("cp.async.commit_group;" ::: "memory")
#define CP_WAIT1()  asm volatile("cp.async.wait_group 1;" ::: "memory")
#define CP_WAIT0()  asm volatile("cp.async.wait_group 0;" ::: "memory")

// ---------------- kernel: build q (single x read, L2 norm, bf16; zeros Z) ----------------
// dynamic smem: 512 x 33 floats = 67584 bytes
__global__ void build_q_kernel(const float* __restrict__ x) {
    extern __shared__ float sx[];            // [512][33]
    int bid = blockIdx.x;
    int n = bid >> 5, h = bid & 31;
    int tid = threadIdx.x;
    int lane = tid & 31, warp = tid >> 5;

    __shared__ float ss[8][32];
    __shared__ float inv[32];

    const float* xb = x + (size_t)n * (CDIM * HDIM * WDIM) + h * WDIM;

    // load x slice once (coalesced), accumulate per-(warp,lane) square sums
    float part = 0.0f;
    for (int c = warp; c < CDIM; c += 8) {
        float v = xb[c * 1024 + lane];
        sx[c * 33 + lane] = v;
        part += v * v;
    }
    ss[warp][lane] = part;
    __syncthreads();
    if (tid < 32) {
        float s = 0.0f;
        #pragma unroll
        for (int g2 = 0; g2 < 8; g2++) s += ss[g2][tid];
        inv[tid] = 1.0f / fmaxf(sqrtf(s), EPSV);
        g_Z[n * 1024 + h * 32 + tid] = 0.0f;
    }
    __syncthreads();

    int t0 = n * 1024 + h * 32;
    for (int tt = warp; tt < 32; tt += 8) {
        float iv = inv[tt];
        #pragma unroll
        for (int c0 = 0; c0 < CDIM; c0 += 64) {
            int c = c0 + lane * 2;
            __nv_bfloat162 pk = __floats2bfloat162_rn(sx[c * 33 + tt] * iv,
                                                      sx[(c + 1) * 33 + tt] * iv);
            *(uint32_t*)&g_qb[(size_t)(t0 + tt) * CDIM + c] = *(uint32_t*)&pk;
        }
    }
}

// ---------------- kernel: MLP GEMM  C = relu(A @ B^T + bias)  (SIMT fp32, 64x64, proven) ----------------
__global__ void mlp_gemm_kernel(const float* __restrict__ extA,
                                const float* __restrict__ Bw,
                                const float* __restrict__ bias,
                                int layer) {
    const float* A = layer ? (const float*)g_h : extA;
    float* Cc      = layer ? g_m : g_h;
    const int M = MEMN;
    const int N = layer ? CDIM : CHID;
    const int K = layer ? CHID : CDIM;

    int n0 = blockIdx.x * 64;
    int m0 = blockIdx.y * 64;

    __shared__ float As[32][68];
    __shared__ float Bs[32][68];

    int tid = threadIdx.x;
    int tx = tid & 15, ty = tid >> 4;
    float acc[4][4] = {};

    for (int k0 = 0; k0 < K; k0 += 32) {
        for (int idx = tid; idx < 512; idx += 256) {
            int r = idx >> 3, kq = (idx & 7) << 2;
            float4 v = make_float4(0.f, 0.f, 0.f, 0.f);
            if (m0 + r < M) v = *(const float4*)&A[(size_t)(m0 + r) * K + k0 + kq];
            As[kq + 0][r] = v.x; As[kq + 1][r] = v.y; As[kq + 2][r] = v.z; As[kq + 3][r] = v.w;
            float4 w = *(const float4*)&Bw[(size_t)(n0 + r) * K + k0 + kq];
            Bs[kq + 0][r] = w.x; Bs[kq + 1][r] = w.y; Bs[kq + 2][r] = w.z; Bs[kq + 3][r] = w.w;
        }
        __syncthreads();
        #pragma unroll
        for (int kk = 0; kk < 32; kk++) {
            float a[4], b[4];
            *(float4*)a = *(const float4*)&As[kk][tx * 4];
            *(float4*)b = *(const float4*)&Bs[kk][ty * 4];
            #pragma unroll
            for (int i = 0; i < 4; i++)
                #pragma unroll
                for (int j = 0; j < 4; j++)
                    acc[i][j] += a[i] * b[j];
        }
        __syncthreads();
    }

    #pragma unroll
    for (int j = 0; j < 4; j++) {
        int col = n0 + ty * 4 + j;
        float bv = bias[col];
        #pragma unroll
        for (int i = 0; i < 4; i++) {
            int row = m0 + tx * 4 + i;
            if (row < M) Cc[(size_t)row * N + col] = fmaxf(acc[i][j] + bv, 0.0f);
        }
    }
}

// ---------------- kernel: row L2-normalize m -> g_mnormb (bf16, zero pad) ----------------
__global__ void norm_rows_kernel() {
    int row = blockIdx.x;
    int tid = threadIdx.x;
    __nv_bfloat16* dst = &g_mnormb[(size_t)row * CDIM];
    if (row >= MEMN) {
        dst[tid] = __float2bfloat16(0.0f);
        dst[tid + 256] = __float2bfloat16(0.0f);
        return;
    }
    const float* src = &g_m[(size_t)row * CDIM];
    float v0 = src[tid], v1 = src[tid + 256];
    float ssv = v0 * v0 + v1 * v1;
    #pragma unroll
    for (int o = 16; o > 0; o >>= 1) ssv += __shfl_down_sync(0xffffffffu, ssv, o);
    __shared__ float red[8];
    __shared__ float sinv;
    if ((tid & 31) == 0) red[tid >> 5] = ssv;
    __syncthreads();
    if (tid == 0) {
        float s = 0.0f;
        #pragma unroll
        for (int i = 0; i < 8; i++) s += red[i];
        sinv = 1.0f / fmaxf(sqrtf(s), EPSV);
    }
    __syncthreads();
    dst[tid] = __float2bfloat16(v0 * sinv);
    dst[tid + 256] = __float2bfloat16(v1 * sinv);
}

// ---------------- kernel: transpose g_mnormb [J,C] -> g_mnormTb [C,J] ----------------
__global__ void transpose_m_kernel() {
    __shared__ __nv_bfloat16 t[32][34];
    int j0 = blockIdx.x * 32, c0 = blockIdx.y * 32;
    int lx = threadIdx.x, ly = threadIdx.y;   // 32 x 8
    #pragma unroll
    for (int ry = 0; ry < 32; ry += 8)
        t[ly + ry][lx] = g_mnormb[(size_t)(j0 + ly + ry) * CDIM + c0 + lx];
    __syncthreads();
    #pragma unroll
    for (int ry = 0; ry < 32; ry += 8)
        g_mnormTb[(size_t)(c0 + ly + ry) * MEMP + j0 + lx] = t[lx][ly + ry];
}

// ================ scores kernel: e = exp(q @ mnorm^T) -> att (fp32), Z sums ==================
// 128 tok x 128 mem tile, K=512, BK=64 (8 stages), cp.async double buffered, ldmatrix.x4
__global__ __launch_bounds__(256, 2) void attn_scores_mma(float* __restrict__ att) {
    extern __shared__ float dsm[];
    float* bufA[2] = { dsm,        dsm + 4608 };
    float* bufB[2] = { dsm + 9216, dsm + 13824 };

    const int j0 = blockIdx.x * 128;
    const int t0 = blockIdx.y * 128;

    __shared__ float zsum[128];

    const int tid = threadIdx.x;
    const int lane = tid & 31, wid = tid >> 5;
    const int wm = wid & 1, wn = wid >> 1;
    const int g = lane >> 2, tg = lane & 3;

    if (tid < 128) zsum[tid] = 0.0f;

    uint32_t aA[2], aB[2];
    aA[0] = (uint32_t)__cvta_generic_to_shared(bufA[0]);
    aA[1] = (uint32_t)__cvta_generic_to_shared(bufA[1]);
    aB[0] = (uint32_t)__cvta_generic_to_shared(bufB[0]);
    aB[1] = (uint32_t)__cvta_generic_to_shared(bufB[1]);

    uint32_t aoff[4], boff[2];
    {
        int lr = lane & 15, lc = lane >> 4;
        #pragma unroll
        for (int i = 0; i < 4; i++)
            aoff[i] = (uint32_t)(((wm * 64 + i * 16 + lr) * WSTRIDE64 + lc * 4) * 4);
        int q = lane >> 3, r8 = lane & 7;
        #pragma unroll
        for (int jp = 0; jp < 2; jp++) {
            int jrow = wn * 32 + (jp * 2 + (q >> 1)) * 8 + r8;
            boff[jp] = (uint32_t)((jrow * WSTRIDE64 + (q & 1) * 4) * 4);
        }
    }

    const int r_ld = tid >> 3, q_ld = tid & 7;

    #pragma unroll
    for (int i = 0; i < 4; i++) {
        int r = r_ld + i * 32;
        uint32_t doff = (uint32_t)(r * WSTRIDE64 + q_ld * 4) * 4;
        cp16(aA[0] + doff, &g_qb[(size_t)(t0 + r) * CDIM + q_ld * 8]);
        cp16(aB[0] + doff, &g_mnormb[(size_t)(j0 + r) * CDIM + q_ld * 8]);
    }
    CP_COMMIT();

    float acc[4][4][4] = {};

    #pragma unroll 1
    for (int it = 0; it < 8; ++it) {
        if (it + 1 < 8) {
            int nb = (it + 1) & 1;
            int k0 = (it + 1) * 64;
            #pragma unroll
            for (int i = 0; i < 4; i++) {
                int r = r_ld + i * 32;
                uint32_t doff = (uint32_t)(r * WSTRIDE64 + q_ld * 4) * 4;
                cp16(aA[nb] + doff, &g_qb[(size_t)(t0 + r) * CDIM + k0 + q_ld * 8]);
                cp16(aB[nb] + doff, &g_mnormb[(size_t)(j0 + r) * CDIM + k0 + q_ld * 8]);
            }
            CP_COMMIT();
            CP_WAIT1();
        } else {
            CP_WAIT0();
        }
        __syncthreads();

        const uint32_t Ab = aA[it & 1];
        const uint32_t Bb = aB[it & 1];
        #pragma unroll
        for (int kh = 0; kh < 4; kh++) {
            uint32_t kbyte = (uint32_t)(kh * 32);
            uint32_t a[4][4], b[4][2];
            #pragma unroll
            for (int i = 0; i < 4; i++)
                LDMATRIX_X4(a[i][0], a[i][1], a[i][2], a[i][3], Ab + aoff[i] + kbyte);
            #pragma unroll
            for (int jp = 0; jp < 2; jp++)
                LDMATRIX_X4(b[jp * 2][0], b[jp * 2][1], b[jp * 2 + 1][0], b[jp * 2 + 1][1],
                            Bb + boff[jp] + kbyte);
            #pragma unroll
            for (int i = 0; i < 4; i++)
                #pragma unroll
                for (int j = 0; j < 4; j++)
                    MMA_BF16(acc[i][j], a[i], b[j]);
        }
        __syncthreads();
    }

    const int n = t0 >> 10, hwb = t0 & 1023;
    #pragma unroll
    for (int i = 0; i < 4; i++) {
        int r0 = wm * 64 + i * 16 + g;
        float z0 = 0.0f, z1 = 0.0f;
        #pragma unroll
        for (int j = 0; j < 4; j++) {
            int cb = wn * 32 + j * 8 + 2 * tg;
            #pragma unroll
            for (int cc = 0; cc < 2; cc++) {
                int jj = j0 + cb + cc;
                if (jj < MEMN) {
                    float e0 = __expf(acc[i][j][cc]);
                    float e1 = __expf(acc[i][j][cc + 2]);
                    size_t base = ((size_t)(n * MEMN + jj)) << 10;
                    att[base + hwb + r0] = e0;
                    att[base + hwb + r0 + 8] = e1;
                    z0 += e0; z1 += e1;
                }
            }
        }
        z0 += __shfl_xor_sync(0xffffffffu, z0, 1);
        z0 += __shfl_xor_sync(0xffffffffu, z0, 2);
        z1 += __shfl_xor_sync(0xffffffffu, z1, 1);
        z1 += __shfl_xor_sync(0xffffffffu, z1, 2);
        if (tg == 0) {
            atomicAdd(&zsum[r0], z0);
            atomicAdd(&zsum[r0 + 8], z1);
        }
    }
    __syncthreads();
    if (tid < 128) atomicAdd(&g_Z[t0 + tid], zsum[tid]);
}

// ================ fused finalize: L1 + flags + att_r in place ==================
// pass 1: stream e, compute L1 + activity flags (kept in a per-thread bitmask)
// pass 2: inactive stages -> write zeros (NO read); active stages -> re-read + transform
__global__ __launch_bounds__(256) void finalize_fused_kernel(float* __restrict__ att) {
    const int t0 = blockIdx.x * 128;
    const int n = t0 >> 10, hw0 = t0 & 1023;
    const int tid = threadIdx.x;
    const int tok = tid & 127, jh = tid >> 7;

    __shared__ float zinv_s[128];
    __shared__ float l1p[256];
    __shared__ float l1inv_s[128];

    if (tid < 128) zinv_s[tid] = 1.0f / g_Z[t0 + tid];
    __syncthreads();

    const float ziv = zinv_s[tok];
    float* ebase = att + (((size_t)n * MEMN) << 10) + hw0 + tok;

    float l1 = 0.0f;
    unsigned long long mask = 0ull;
    #pragma unroll 1
    for (int st = 0; st < 64; st++) {
        int jb = st * 32 + jh * 16;
        int flag = 0;
        #pragma unroll
        for (int i = 0; i < 16; i++) {
            int j = jb + i;
            float e = (j < MEMN) ? ebase[(size_t)j << 10] : 0.0f;
            float p = fmaxf(e * ziv - SHRINK, 0.0f);
            l1 += p;
            flag |= (p > 0.0f);
        }
        int act = __syncthreads_or(flag);
        mask |= (unsigned long long)(act != 0) << st;
        if (tid == 0) g_flags[blockIdx.x * 64 + st] = act;
    }

    l1p[tid] = l1;
    __syncthreads();
    if (tid < 128) l1inv_s[tid] = 1.0f / fmaxf(l1p[tid] + l1p[tid + 128], EPSV);
    __syncthreads();
    const float l1i = l1inv_s[tok];

    #pragma unroll 1
    for (int st = 0; st < 64; st++) {
        int jb = st * 32 + jh * 16;
        if (!((mask >> st) & 1ull)) {
            #pragma unroll
            for (int i = 0; i < 16; i++) {
                int j = jb + i;
                if (j < MEMN) ebase[(size_t)j << 10] = 0.0f;
            }
        } else {
            #pragma unroll
            for (int i = 0; i < 16; i++) {
                int j = jb + i;
                if (j < MEMN) {
                    float e = ebase[(size_t)j << 10];
                    ebase[(size_t)j << 10] = fmaxf(e * ziv - SHRINK, 0.0f) * l1i;
                }
            }
        }
    }
}

// ================ out kernel: out = att_r @ mnorm, flag-gated stages ==================
// A = finalized att_r (converted to bf16 on load); no Z/L1 anywhere
__global__ __launch_bounds__(256, 2) void attn_out_mma(const float* __restrict__ att,
                                                       float* __restrict__ out) {
    extern __shared__ float dsm[];
    float* sA = dsm;                       // [128 tok][20 words] bf16 A-tile
    float* bufB[2] = { dsm + 2560, dsm + 5120 };

    const int c0b = blockIdx.x * 128;
    const int t0 = blockIdx.y * 128;
    const int n = t0 >> 10, hw0 = t0 & 1023;

    __shared__ int sflags[64];

    const int tid = threadIdx.x;
    const int lane = tid & 31, wid = tid >> 5;
    const int wm = wid & 1, wn = wid >> 1;
    const int g = lane >> 2, tg = lane & 3;

    if (tid < 64) sflags[tid] = g_flags[blockIdx.y * 64 + tid];
    __syncthreads();

    const int tok = tid & 127, jh = tid >> 7;
    const float* ebase = att + (((size_t)n * MEMN) << 10) + hw0 + tok;

    uint32_t aB[2];
    aB[0] = (uint32_t)__cvta_generic_to_shared(bufB[0]);
    aB[1] = (uint32_t)__cvta_generic_to_shared(bufB[1]);
    const int r_ld = tid >> 2, q_ld = tid & 3;

    float ar[16];
    uint32_t* sAw = (uint32_t*)sA;

    // prologue: stage 0 (only if active)
    if (sflags[0]) {
        #pragma unroll
        for (int i = 0; i < 16; i++) {
            int j = jh * 16 + i;
            ar[i] = (j < MEMN) ? ebase[(size_t)j << 10] : 0.0f;
        }
        #pragma unroll
        for (int i = 0; i < 2; i++) {
            int r = r_ld + i * 64;
            uint32_t doff = (uint32_t)(r * WSTRIDE + q_ld * 4) * 4;
            cp16(aB[0] + doff, &g_mnormTb[(size_t)(c0b + r) * MEMP + q_ld * 8]);
        }
    }
    CP_COMMIT();
    if (sflags[0]) {
        #pragma unroll
        for (int i = 0; i < 8; i++) {
            __nv_bfloat162 pk = __floats2bfloat162_rn(ar[2 * i], ar[2 * i + 1]);
            sAw[tok * WSTRIDE + jh * 8 + i] = *(uint32_t*)&pk;
        }
    }

    float acc[4][4][4] = {};

    #pragma unroll 1
    for (int it = 0; it < 64; ++it) {
        int nxt_active = 0;
        if (it + 1 < 64) {
            nxt_active = sflags[it + 1];
            if (nxt_active) {
                int nb = (it + 1) & 1;
                int k0 = (it + 1) * 32;
                #pragma unroll
                for (int i = 0; i < 2; i++) {
                    int r = r_ld + i * 64;
                    uint32_t doff = (uint32_t)(r * WSTRIDE + q_ld * 4) * 4;
                    cp16(aB[nb] + doff, &g_mnormTb[(size_t)(c0b + r) * MEMP + k0 + q_ld * 8]);
                }
            }
            CP_COMMIT();   // empty group when inactive — keeps group counting consistent
            if (nxt_active) {
                int k0 = (it + 1) * 32;
                #pragma unroll
                for (int i = 0; i < 16; i++) {
                    int j = k0 + jh * 16 + i;
                    ar[i] = (j < MEMN) ? ebase[(size_t)j << 10] : 0.0f;
                }
            }
            CP_WAIT1();
        } else {
            CP_WAIT0();
        }
        __syncthreads();   // sA stores + B(it) visible

        if (sflags[it]) {
            const uint32_t* Bs = (const uint32_t*)bufB[it & 1];
            #pragma unroll
            for (int kh = 0; kh < 2; kh++) {
                int ko = kh * 8;
                uint32_t a[4][4], b[4][2];
                #pragma unroll
                for (int i = 0; i < 4; i++) {
                    const uint32_t* ap = &sAw[(wm * 64 + i * 16 + g) * WSTRIDE + ko + tg];
                    a[i][0] = ap[0];
                    a[i][1] = ap[8 * WSTRIDE];
                    a[i][2] = ap[4];
                    a[i][3] = ap[8 * WSTRIDE + 4];
                }
                #pragma unroll
                for (int j = 0; j < 4; j++) {
                    const uint32_t* bp = &Bs[(wn * 32 + j * 8 + g) * WSTRIDE + ko + tg];
                    b[j][0] = bp[0];
                    b[j][1] = bp[4];
                }
                #pragma unroll
                for (int i = 0; i < 4; i++)
                    #pragma unroll
                    for (int j = 0; j < 4; j++)
                        MMA_BF16(acc[i][j], a[i], b[j]);
            }
        }
        __syncthreads();   // MMA reads of sA done before overwrite

        if (nxt_active) {
            #pragma unroll
            for (int i = 0; i < 8; i++) {
                __nv_bfloat162 pk = __floats2bfloat162_rn(ar[2 * i], ar[2 * i + 1]);
                sAw[tok * WSTRIDE + jh * 8 + i] = *(uint32_t*)&pk;
            }
        }
    }

    // epilogue: write out NCHW (A was already att_r = p/L1 — no scaling)
    #pragma unroll
    for (int i = 0; i < 4; i++) {
        int r0 = wm * 64 + i * 16 + g;
        #pragma unroll
        for (int j = 0; j < 4; j++) {
            int cb = c0b + wn * 32 + j * 8 + 2 * tg;
            #pragma unroll
            for (int cc = 0; cc < 2; cc++) {
                size_t base = ((size_t)(n * CDIM + cb + cc)) << 10;
                out[base + hw0 + r0]     = acc[i][j][cc];
                out[base + hw0 + r0 + 8] = acc[i][j][cc + 2];
            }
        }
    }
}

// ---------------- launch ----------------
extern "C" void kernel_launch(void* const* d_in, const int* in_sizes, int n_in,
                              void* d_out, int out_size) {
    const float* x      = (const float*)d_in[0];
    const float* memory = (const float*)d_in[1];
    const float* w1     = (const float*)d_in[2];
    const float* b1     = (const float*)d_in[3];
    const float* w2     = (const float*)d_in[4];
    const float* b2     = (const float*)d_in[5];

    float* out = (float*)d_out;
    float* att = out + OUT_ELEMS;

    cudaFuncSetAttribute(attn_scores_mma, cudaFuncAttributeMaxDynamicSharedMemorySize, 73728);
    cudaFuncSetAttribute(build_q_kernel,  cudaFuncAttributeMaxDynamicSharedMemorySize, 67584);

    build_q_kernel<<<NIMG * HDIM, 256, 67584>>>(x);
    mlp_gemm_kernel<<<dim3(CHID / 64, (MEMN + 63) / 64), 256>>>(memory, w1, b1, 0);
    mlp_gemm_kernel<<<dim3(CDIM / 64, (MEMN + 63) / 64), 256>>>(nullptr, w2, b2, 1);
    norm_rows_kernel<<<MEMP, 256>>>();
    transpose_m_kernel<<<dim3(MEMP / 32, CDIM / 32), dim3(32, 8)>>>();
    attn_scores_mma<<<dim3(MEMP / 128, TTOK / 128), 256, 73728>>>(att);
    finalize_fused_kernel<<<TTOK / 128, 256>>>(att);
    attn_out_mma<<<dim3(CDIM / 128, TTOK / 128), 256, 30720>>>(att, out);
}